// round 11
// baseline (speedup 1.0000x reference)
#include <cuda_runtime.h>
#include <math.h>

#define BB   4
#define NN   4096
#define CC   128
#define KK1  16
#define KK2  8
#define TDD  64
#define KDIM 131
#define KPAD 144
#define RWS  512
#define NPTS (BB*NN)

typedef unsigned long long u64;

__device__ __forceinline__ u64 ffma2(u64 a, u64 b, u64 c) {
    u64 d;
    asm("fma.rn.f32x2 %0, %1, %2, %3;" : "=l"(d) : "l"(a), "l"(b), "l"(c));
    return d;
}
__device__ __forceinline__ u64 dup2(float x) {
    u64 d;
    asm("mov.b64 %0, {%1, %1};" : "=l"(d) : "r"(__float_as_int(x)));
    return d;
}
__device__ __forceinline__ void unpack2(u64 v, float& lo, float& hi) {
    int a, b;
    asm("mov.b64 {%0, %1}, %2;" : "=r"(a), "=r"(b) : "l"(v));
    lo = __int_as_float(a); hi = __int_as_float(b);
}

// ---------------- scratch ----------------
__device__ int    g_idx[NPTS*KK1];
__device__ float4 g_xyzw[NPTS];                // packed (x,y,z,|x|^2)
// per point rows: [0:64)Pq [64:128)Pk [128:256)PvProj [256:320)Sq [320:384)Sk [384:512)SvProj
__device__ float g_P[(size_t)NPTS*RWS];
__device__ float g_WcT[KPAD*RWS];
__device__ float g_bias[RWS];

// ---------------- pack: xyz rows -> float4 with |x|^2 ----------------
__global__ void pack_kernel(const float* __restrict__ xyz) {
    int i = blockIdx.x * blockDim.x + threadIdx.x;
    if (i >= NPTS) return;
    int b = i >> 12, n = i & (NN - 1);
    const float* xb = xyz + (size_t)b * 3 * NN;
    float x = xb[n], y = xb[NN + n], z = xb[2 * NN + n];
    float sq = fmaf(z, z, fmaf(y, y, x * x));
    g_xyzw[i] = make_float4(x, y, z, sq);
}

// ---------------- prep ----------------
__global__ void prep_kernel(const float* __restrict__ wq, const float* __restrict__ wk,
                            const float* __restrict__ wv, const float* __restrict__ bq,
                            const float* __restrict__ bk, const float* __restrict__ bv,
                            const float* __restrict__ w1) {
    int i = blockIdx.x * blockDim.x + threadIdx.x;
    const int total1 = KPAD * RWS;
    if (i < total1) {
        int k = i >> 9;
        int r = i & 511;
        float val = 0.f;
        if (k < KDIM) {
            if (r < 128) {                       // Pq | Pk
                const float* w = (r < 64) ? wq : wk;
                const float* row = w + (r & 63) * 262;
                val = (k < 3) ? row[k] : row[6 + (k - 3)];
            } else if (r < 256) {                // PvProj = w1 @ Pv
                int o = r - 128;
                float s = 0.f;
                for (int m = 0; m < TDD; ++m) {
                    const float* row = wv + m * 262;
                    float wvk = (k < 3) ? row[k] : row[6 + (k - 3)];
                    s = fmaf(w1[o * TDD + m], wvk, s);
                }
                val = s;
            } else if (r < 384) {                // Sq | Sk
                const float* w = (r < 320) ? wq : wk;
                const float* row = w + (r & 63) * 262;
                val = (k < 3) ? (row[3 + k] - row[k])
                              : (row[134 + (k - 3)] - row[6 + (k - 3)]);
            } else {                             // SvProj = w1 @ Sv
                int o = r - 384;
                float s = 0.f;
                for (int m = 0; m < TDD; ++m) {
                    const float* row = wv + m * 262;
                    float d = (k < 3) ? (row[3 + k] - row[k])
                                      : (row[134 + (k - 3)] - row[6 + (k - 3)]);
                    s = fmaf(w1[o * TDD + m], d, s);
                }
                val = s;
            }
        }
        g_WcT[(k << 9) + r] = val;
        return;
    }
    i -= total1;
    if (i < RWS) {
        float bval = 0.f;
        if (i >= 256 && i < 320) bval = bq[i - 256];
        else if (i >= 320 && i < 384) bval = bk[i - 320];
        else if (i >= 384) {
            int o = i - 384;
            float s = 0.f;
            for (int m = 0; m < TDD; ++m) s = fmaf(w1[o * TDD + m], bv[m], s);
            bval = s;
        }
        g_bias[i] = bval;
    }
}

// ---------------- kNN (per batch): warp per 2 queries, smem-free ----------------
// Self is NOT excluded: d(self) = -|q|^2 is the strict minimum -> rank 0 always.
// Emit ranks 1..16 of a top-17 list.
__global__ __launch_bounds__(512) void knn_kernel(int b) {
    const unsigned FULL = 0xffffffffu;
    const int qbase = blockIdx.x * 32;             // 128 blocks per batch
    const int tid = threadIdx.x;
    const int w = tid >> 5, lane = tid & 31;
    const float4* __restrict__ cb = g_xyzw + (size_t)b * NN;

    const int qAi = qbase + 2 * w;
    const int qBi = qAi + 1;
    const float4 qA = cb[qAi];
    const float4 qB = cb[qBi];

    // ---- t = 0: evaluate first 32 candidates for both queries ----
    float dlA, dlB;
    int   ilA = lane, ilB = lane;
    {
        float4 c = __ldg(cb + lane);
        dlA = fmaf(-2.0f, fmaf(qA.z, c.z, fmaf(qA.y, c.y, qA.x * c.x)), c.w);
        dlB = fmaf(-2.0f, fmaf(qB.z, c.z, fmaf(qB.y, c.y, qB.x * c.x)), c.w);
    }
    // fused bitonic sort across lanes for both lists (asc by dist, idx tie-break)
#pragma unroll
    for (int k = 2; k <= 32; k <<= 1) {
#pragma unroll
        for (int j = k >> 1; j > 0; j >>= 1) {
            float odA = __shfl_xor_sync(FULL, dlA, j);
            int   oiA = __shfl_xor_sync(FULL, ilA, j);
            float odB = __shfl_xor_sync(FULL, dlB, j);
            int   oiB = __shfl_xor_sync(FULL, ilB, j);
            bool keepLt = (((lane & k) == 0) == ((lane & j) == 0));
            bool ltA = (odA < dlA) || (odA == dlA && oiA < ilA);
            bool ltB = (odB < dlB) || (odB == dlB && oiB < ilB);
            bool swA = keepLt ? ltA : !ltA;
            bool swB = keepLt ? ltB : !ltB;
            if (swA) { dlA = odA; ilA = oiA; }
            if (swB) { dlB = odB; ilB = oiB; }
        }
    }
    float kthA = __shfl_sync(FULL, dlA, 16);   // 17th smallest
    float kthB = __shfl_sync(FULL, dlB, 16);

    // ---- main scan: one LDG.128 per candidate serves both queries ----
#pragma unroll 2
    for (int t = 1; t < NN / 32; ++t) {
        const float4 c = __ldg(cb + t * 32 + lane);
        float dA = fmaf(-2.0f, fmaf(qA.z, c.z, fmaf(qA.y, c.y, qA.x * c.x)), c.w);
        float dB = fmaf(-2.0f, fmaf(qB.z, c.z, fmaf(qB.y, c.y, qB.x * c.x)), c.w);

        unsigned mA = __ballot_sync(FULL, dA < kthA);
        unsigned mB = __ballot_sync(FULL, dB < kthB);
        if (mA) {
            do {
                const int src = __ffs(mA) - 1;
                mA &= mA - 1;
                const float dc = __shfl_sync(FULL, dA, src);
                const int   mc = t * 32 + src;
                const float up_d = __shfl_up_sync(FULL, dlA, 1);
                const int   up_i = __shfl_up_sync(FULL, ilA, 1);
                const bool here = dc < dlA;                 // strict: stable tie-break
                const bool prev = (lane > 0) && (dc < up_d);
                dlA = here ? (prev ? up_d : dc) : dlA;
                ilA = here ? (prev ? up_i : mc) : ilA;
            } while (mA);
            kthA = __shfl_sync(FULL, dlA, 16);
        }
        if (mB) {
            do {
                const int src = __ffs(mB) - 1;
                mB &= mB - 1;
                const float dc = __shfl_sync(FULL, dB, src);
                const int   mc = t * 32 + src;
                const float up_d = __shfl_up_sync(FULL, dlB, 1);
                const int   up_i = __shfl_up_sync(FULL, ilB, 1);
                const bool here = dc < dlB;
                const bool prev = (lane > 0) && (dc < up_d);
                dlB = here ? (prev ? up_d : dc) : dlB;
                ilB = here ? (prev ? up_i : mc) : ilB;
            } while (mB);
            kthB = __shfl_sync(FULL, dlB, 16);
        }
    }

    // ranks 1..16 (rank 0 == self)
    if (lane >= 1 && lane <= KK1) {
        g_idx[((size_t)b * NN + qAi) * KK1 + (lane - 1)] = ilA;
        g_idx[((size_t)b * NN + qBi) * KK1 + (lane - 1)] = ilB;
    }
}

// ---------------- SGEMM (per batch) with packed f32x2 FMA ----------------
__global__ __launch_bounds__(256, 2) void gemm_kernel(const float* __restrict__ xyz,
                                                      const float* __restrict__ feature,
                                                      int b) {
    __shared__ __align__(16) float As[16][128];
    __shared__ __align__(16) float Bs[16][128];

    const int tid = threadIdx.x;
    const int tr = tid >> 4;
    const int tc = tid & 15;
    const int nl = blockIdx.x * 128;               // 32 blocks per batch
    const int rowbase = blockIdx.y * 128;

    const int la_k = tid >> 4;
    const int la_r = (tid & 15) * 8;
    const int lb_k = tid >> 4;
    const int lb_j = (tid & 15) * 8;

    u64 acc[8][4];
#pragma unroll
    for (int i = 0; i < 8; ++i)
#pragma unroll
        for (int j = 0; j < 4; ++j) acc[i][j] = 0ull;

    float4 pa0, pa1, pb0, pb1;
    {
        const float* srcA = g_WcT + la_k * RWS + rowbase + la_r;
        pa0 = *(const float4*)srcA; pa1 = *(const float4*)(srcA + 4);
        int kg = lb_k;
        const float* row = (kg < 3) ? (xyz + ((size_t)b * 3 + kg) * NN)
                                    : (feature + ((size_t)b * CC + (kg - 3)) * NN);
        pb0 = *(const float4*)(row + nl + lb_j);
        pb1 = *(const float4*)(row + nl + lb_j + 4);
    }

    for (int kt = 0; kt < KPAD / 16; ++kt) {
        *(float4*)&As[la_k][la_r]     = pa0;
        *(float4*)&As[la_k][la_r + 4] = pa1;
        *(float4*)&Bs[lb_k][lb_j]     = pb0;
        *(float4*)&Bs[lb_k][lb_j + 4] = pb1;
        __syncthreads();
        if (kt + 1 < KPAD / 16) {
            const float* srcA = g_WcT + ((kt + 1) * 16 + la_k) * RWS + rowbase + la_r;
            pa0 = *(const float4*)srcA; pa1 = *(const float4*)(srcA + 4);
            int kg = (kt + 1) * 16 + lb_k;
            if (kg < KDIM) {
                const float* row = (kg < 3) ? (xyz + ((size_t)b * 3 + kg) * NN)
                                            : (feature + ((size_t)b * CC + (kg - 3)) * NN);
                pb0 = *(const float4*)(row + nl + lb_j);
                pb1 = *(const float4*)(row + nl + lb_j + 4);
            } else {
                pb0 = make_float4(0.f, 0.f, 0.f, 0.f);
                pb1 = pb0;
            }
        }
#pragma unroll
        for (int k = 0; k < 16; ++k) {
            float4 a0 = *(const float4*)&As[k][tr * 8];
            float4 a1 = *(const float4*)&As[k][tr * 8 + 4];
            ulonglong2 b0 = *(const ulonglong2*)&Bs[k][tc * 8];
            ulonglong2 b1 = *(const ulonglong2*)&Bs[k][tc * 8 + 4];
            u64 bp[4] = {b0.x, b0.y, b1.x, b1.y};
            float ar[8] = {a0.x, a0.y, a0.z, a0.w, a1.x, a1.y, a1.z, a1.w};
#pragma unroll
            for (int i = 0; i < 8; ++i) {
                u64 a2 = dup2(ar[i]);
#pragma unroll
                for (int j = 0; j < 4; ++j)
                    acc[i][j] = ffma2(a2, bp[j], acc[i][j]);
            }
        }
        __syncthreads();
    }

    const int gr = rowbase + tr * 8;
    float bias[8];
#pragma unroll
    for (int i = 0; i < 8; ++i) bias[i] = g_bias[gr + i];
    float r_[8][8];
#pragma unroll
    for (int i = 0; i < 8; ++i)
#pragma unroll
        for (int j = 0; j < 4; ++j)
            unpack2(acc[i][j], r_[i][2 * j], r_[i][2 * j + 1]);
#pragma unroll
    for (int j = 0; j < 8; ++j) {
        int p = b * NN + nl + tc * 8 + j;
        float* dst = g_P + (size_t)p * RWS + gr;
        float4 v0 = make_float4(r_[0][j] + bias[0], r_[1][j] + bias[1],
                                r_[2][j] + bias[2], r_[3][j] + bias[3]);
        float4 v1 = make_float4(r_[4][j] + bias[4], r_[5][j] + bias[5],
                                r_[6][j] + bias[6], r_[7][j] + bias[7]);
        *(float4*)dst       = v0;
        *(float4*)(dst + 4) = v1;
    }
}

// ---------------- attention (per batch) ----------------
#define WARP_FLOATS 1632
#define SM_RES      (8*WARP_FLOATS)
#define SM_ATTN_TOT (SM_RES + 8*132)

__global__ __launch_bounds__(256, 3) void attn_kernel(const float* __restrict__ feature,
                                                      const float* __restrict__ b1,
                                                      float* __restrict__ out,
                                                      int bb) {
    extern __shared__ __align__(16) float sm[];
    const int tid = threadIdx.x;
    const int w = tid >> 5, l = tid & 31;
    float* qw   = sm + w * WARP_FLOATS;
    float* kw   = qw + 8 * 68;
    float* resT = sm + SM_RES;

    const int lp = blockIdx.x * 8 + w;             // point index within batch (512 blocks)
    const int gp = (bb << 12) + lp;
    const int* ip = g_idx + (size_t)gp * KK1;
    const float* Pbase = g_P + ((size_t)(bb << 12)) * RWS;
    const float* Sp    = g_P + (size_t)gp * RWS + 256;

    int c[16];
    {
        int4 t0 = ((const int4*)ip)[0]; int4 t1 = ((const int4*)ip)[1];
        int4 t2 = ((const int4*)ip)[2]; int4 t3 = ((const int4*)ip)[3];
        c[0]=t0.x; c[1]=t0.y; c[2]=t0.z; c[3]=t0.w;
        c[4]=t1.x; c[5]=t1.y; c[6]=t1.z; c[7]=t1.w;
        c[8]=t2.x; c[9]=t2.y; c[10]=t2.z; c[11]=t2.w;
        c[12]=t3.x; c[13]=t3.y; c[14]=t3.z; c[15]=t3.w;
    }

    // ---- gather q = Pq[c] + Sq ----
    {
        int a = l >> 2, qt = l & 3;
        const float4* src = (const float4*)(Pbase + (size_t)c[a] * RWS) + qt * 4;
        const float4* s4  = (const float4*)Sp + qt * 4;
        float4* dst = (float4*)(qw + a * 68 + qt * 16);
#pragma unroll
        for (int f = 0; f < 4; ++f) {
            float4 p = src[f], s = s4[f];
            dst[f] = make_float4(p.x + s.x, p.y + s.y, p.z + s.z, p.w + s.w);
        }
    }
    // ---- gather k = Pk[c] + Sk ----
    {
        int j = l >> 1, h = l & 1;
        const float4* src = (const float4*)(Pbase + (size_t)c[j] * RWS + 64 + h * 32);
        const float4* s4  = (const float4*)(Sp + 64 + h * 32);
        float4* dst = (float4*)(kw + j * 68 + h * 32);
#pragma unroll
        for (int f = 0; f < 8; ++f) {
            float4 p = src[f], s = s4[f];
            dst[f] = make_float4(p.x + s.x, p.y + s.y, p.z + s.z, p.w + s.w);
        }
    }
    __syncwarp();

    // ---- logits with packed f32x2 ----
    const int nq = l & 7, jg = l >> 3;
    u64 acc2[4] = {0ull, 0ull, 0ull, 0ull};
    const ulonglong2* qrow = (const ulonglong2*)(qw + nq * 68);
#pragma unroll
    for (int dc = 0; dc < 4; ++dc) {
        ulonglong2 qa = qrow[dc * 4 + 0], qb = qrow[dc * 4 + 1];
        ulonglong2 qc = qrow[dc * 4 + 2], qd = qrow[dc * 4 + 3];
#pragma unroll
        for (int j4 = 0; j4 < 4; ++j4) {
            const ulonglong2* kr = (const ulonglong2*)(kw + (j4 * 4 + jg) * 68);
            ulonglong2 ka = kr[dc * 4 + 0], kb = kr[dc * 4 + 1];
            ulonglong2 kc = kr[dc * 4 + 2], kd = kr[dc * 4 + 3];
            u64 s = acc2[j4];
            s = ffma2(qa.x, ka.x, s); s = ffma2(qa.y, ka.y, s);
            s = ffma2(qb.x, kb.x, s); s = ffma2(qb.y, kb.y, s);
            s = ffma2(qc.x, kc.x, s); s = ffma2(qc.y, kc.y, s);
            s = ffma2(qd.x, kd.x, s); s = ffma2(qd.y, kd.y, s);
            acc2[j4] = s;
        }
    }
    float acc[4];
#pragma unroll
    for (int j4 = 0; j4 < 4; ++j4) {
        float lo, hi; unpack2(acc2[j4], lo, hi);
        acc[j4] = lo + hi;
    }

    // ---- softmax over j per query row nq ----
    float mx = fmaxf(fmaxf(acc[0], acc[1]), fmaxf(acc[2], acc[3]));
    mx = fmaxf(mx, __shfl_xor_sync(0xffffffffu, mx, 8));
    mx = fmaxf(mx, __shfl_xor_sync(0xffffffffu, mx, 16));
    float e[4], ssum = 0.f;
#pragma unroll
    for (int j4 = 0; j4 < 4; ++j4) { e[j4] = __expf(acc[j4] - mx); ssum += e[j4]; }
    ssum += __shfl_xor_sync(0xffffffffu, ssum, 8);
    ssum += __shfl_xor_sync(0xffffffffu, ssum, 16);
    float inv = 1.0f / ssum;
    float wj[4];
#pragma unroll
    for (int j4 = 0; j4 < 4; ++j4) wj[j4] = e[j4] * inv;

    // ---- colsum over the 8 queries ----
#pragma unroll
    for (int off = 1; off < 8; off <<= 1)
#pragma unroll
        for (int j4 = 0; j4 < 4; ++j4)
            wj[j4] += __shfl_xor_sync(0xffffffffu, wj[j4], off);

    // ---- res128 = sum_j w[j]*PvProj[c_j] + wsum*SvProj (packed) ----
    u64 av0 = 0ull, av1 = 0ull;
#pragma unroll
    for (int j = 0; j < 16; ++j) {
        float wjv = __shfl_sync(0xffffffffu, wj[j >> 2], (j & 3) * 8);
        u64 w2 = dup2(wjv);
        ulonglong2 vv = *(const ulonglong2*)(Pbase + (size_t)c[j] * RWS + 128 + 4 * l);
        av0 = ffma2(w2, vv.x, av0);
        av1 = ffma2(w2, vv.y, av1);
    }
    float wsum = wj[0] + wj[1] + wj[2] + wj[3];
    wsum += __shfl_xor_sync(0xffffffffu, wsum, 8);
    wsum += __shfl_xor_sync(0xffffffffu, wsum, 16);
    {
        u64 w2 = dup2(wsum);
        ulonglong2 sv = *(const ulonglong2*)(Sp + 128 + 4 * l);
        av0 = ffma2(w2, sv.x, av0);
        av1 = ffma2(w2, sv.y, av1);
    }
    {
        float4 r;
        unpack2(av0, r.x, r.y);
        unpack2(av1, r.z, r.w);
        *(float4*)(resT + w * 132 + 4 * l) = r;
    }
    __syncthreads();

    // ---- out = res + b1 + feature ----
    const int o  = tid >> 1;
    const int pg = (tid & 1) * 4;
    const int nl = blockIdx.x * 8;
    size_t base = ((size_t)bb * CC + o) * NN + nl + pg;
    float bo = b1[o];
    float4 fv = *(const float4*)(feature + base);
    float4 ov;
    ov.x = resT[(pg + 0) * 132 + o] + bo + fv.x;
    ov.y = resT[(pg + 1) * 132 + o] + bo + fv.y;
    ov.z = resT[(pg + 2) * 132 + o] + bo + fv.z;
    ov.w = resT[(pg + 3) * 132 + o] + bo + fv.w;
    *(float4*)(out + base) = ov;
}

// ---------------- launch: per-batch software pipeline across 3 streams ----------------
extern "C" void kernel_launch(void* const* d_in, const int* in_sizes, int n_in,
                              void* d_out, int out_size) {
    const float* feature = (const float*)d_in[0];
    const float* xyz     = (const float*)d_in[1];
    const float* wq      = (const float*)d_in[2];
    const float* bq      = (const float*)d_in[3];
    const float* wk      = (const float*)d_in[4];
    const float* bk      = (const float*)d_in[5];
    const float* wv      = (const float*)d_in[6];
    const float* bv      = (const float*)d_in[7];
    const float* w1      = (const float*)d_in[8];
    const float* b1      = (const float*)d_in[9];
    float* out = (float*)d_out;

    static cudaStream_t s_aux = []{
        cudaStream_t s; cudaStreamCreateWithFlags(&s, cudaStreamNonBlocking); return s; }();
    static cudaStream_t s_attn = []{
        cudaStream_t s; cudaStreamCreateWithFlags(&s, cudaStreamNonBlocking); return s; }();
    static cudaEvent_t ev_fork = []{
        cudaEvent_t e; cudaEventCreateWithFlags(&e, cudaEventDisableTiming); return e; }();
    static cudaEvent_t ev_done = []{
        cudaEvent_t e; cudaEventCreateWithFlags(&e, cudaEventDisableTiming); return e; }();
    static cudaEvent_t ev_knn[BB] = {};
    static cudaEvent_t ev_gemm[BB] = {};
    static bool init_done = []{
        for (int b = 0; b < BB; ++b) {
            cudaEventCreateWithFlags(&ev_knn[b],  cudaEventDisableTiming);
            cudaEventCreateWithFlags(&ev_gemm[b], cudaEventDisableTiming);
        }
        cudaFuncSetAttribute(attn_kernel, cudaFuncAttributeMaxDynamicSharedMemorySize, SM_ATTN_TOT * 4);
        return true; }();
    (void)init_done;

    const int attn_smem = SM_ATTN_TOT * 4;

    cudaEventRecord(ev_fork, 0);
    cudaStreamWaitEvent(s_aux, ev_fork, 0);

    // aux branch: prep -> gemm per batch
    {
        int total = KPAD * RWS + RWS;
        prep_kernel<<<(total + 255) / 256, 256, 0, s_aux>>>(wq, wk, wv, bq, bk, bv, w1);
    }
    for (int b = 0; b < BB; ++b) {
        gemm_kernel<<<dim3(NN / 128, RWS / 128), 256, 0, s_aux>>>(xyz, feature, b);
        cudaEventRecord(ev_gemm[b], s_aux);
    }

    // main branch: pack -> knn per batch
    pack_kernel<<<(NPTS + 255) / 256, 256>>>(xyz);
    for (int b = 0; b < BB; ++b) {
        knn_kernel<<<128, 512>>>(b);
        cudaEventRecord(ev_knn[b], 0);
    }

    // attn stream: fire each batch as soon as its knn + gemm are done
    for (int b = 0; b < BB; ++b) {
        cudaStreamWaitEvent(s_attn, ev_knn[b], 0);
        cudaStreamWaitEvent(s_attn, ev_gemm[b], 0);
        attn_kernel<<<NN / 8, 256, attn_smem, s_attn>>>(feature, b1, out, b);
    }

    cudaEventRecord(ev_done, s_attn);
    cudaStreamWaitEvent(0, ev_done, 0);
}

// round 12
// speedup vs baseline: 1.1765x; 1.1765x over previous
#include <cuda_runtime.h>
#include <math.h>

#define BB   4
#define NN   4096
#define CC   128
#define KK1  16
#define KK2  8
#define TDD  64
#define KDIM 131
#define KPAD 144
#define RWS  512
#define NPTS (BB*NN)

typedef unsigned long long u64;

__device__ __forceinline__ u64 ffma2(u64 a, u64 b, u64 c) {
    u64 d;
    asm("fma.rn.f32x2 %0, %1, %2, %3;" : "=l"(d) : "l"(a), "l"(b), "l"(c));
    return d;
}
__device__ __forceinline__ u64 dup2(float x) {
    u64 d;
    asm("mov.b64 %0, {%1, %1};" : "=l"(d) : "r"(__float_as_int(x)));
    return d;
}
__device__ __forceinline__ void unpack2(u64 v, float& lo, float& hi) {
    int a, b;
    asm("mov.b64 {%0, %1}, %2;" : "=r"(a), "=r"(b) : "l"(v));
    lo = __int_as_float(a); hi = __int_as_float(b);
}

// ---------------- scratch ----------------
__device__ int   g_idx[NPTS*KK1];
// per point rows: [0:64)Pq [64:128)Pk [128:256)PvProj [256:320)Sq [320:384)Sk [384:512)SvProj
__device__ float g_P[(size_t)NPTS*RWS];
__device__ float g_WcT[KPAD*RWS];
__device__ float g_bias[RWS];

// ---------------- prep ----------------
__global__ void prep_kernel(const float* __restrict__ wq, const float* __restrict__ wk,
                            const float* __restrict__ wv, const float* __restrict__ bq,
                            const float* __restrict__ bk, const float* __restrict__ bv,
                            const float* __restrict__ w1) {
    int i = blockIdx.x * blockDim.x + threadIdx.x;
    const int total1 = KPAD * RWS;
    if (i < total1) {
        int k = i >> 9;
        int r = i & 511;
        float val = 0.f;
        if (k < KDIM) {
            if (r < 128) {                       // Pq | Pk
                const float* w = (r < 64) ? wq : wk;
                const float* row = w + (r & 63) * 262;
                val = (k < 3) ? row[k] : row[6 + (k - 3)];
            } else if (r < 256) {                // PvProj = w1 @ Pv
                int o = r - 128;
                float s = 0.f;
                for (int m = 0; m < TDD; ++m) {
                    const float* row = wv + m * 262;
                    float wvk = (k < 3) ? row[k] : row[6 + (k - 3)];
                    s = fmaf(w1[o * TDD + m], wvk, s);
                }
                val = s;
            } else if (r < 384) {                // Sq | Sk
                const float* w = (r < 320) ? wq : wk;
                const float* row = w + (r & 63) * 262;
                val = (k < 3) ? (row[3 + k] - row[k])
                              : (row[134 + (k - 3)] - row[6 + (k - 3)]);
            } else {                             // SvProj = w1 @ Sv
                int o = r - 384;
                float s = 0.f;
                for (int m = 0; m < TDD; ++m) {
                    const float* row = wv + m * 262;
                    float d = (k < 3) ? (row[3 + k] - row[k])
                                      : (row[134 + (k - 3)] - row[6 + (k - 3)]);
                    s = fmaf(w1[o * TDD + m], d, s);
                }
                val = s;
            }
        }
        g_WcT[(k << 9) + r] = val;
        return;
    }
    i -= total1;
    if (i < RWS) {
        float bval = 0.f;
        if (i >= 256 && i < 320) bval = bq[i - 256];
        else if (i >= 320 && i < 384) bval = bk[i - 320];
        else if (i >= 384) {
            int o = i - 384;
            float s = 0.f;
            for (int m = 0; m < TDD; ++m) s = fmaf(w1[o * TDD + m], bv[m], s);
            bval = s;
        }
        g_bias[i] = bval;
    }
}

// ---------------- kNN (per batch): warp per 2 queries, smem tile, top-17 ----------------
// Self is NOT excluded: d(self) = -|q|^2 is the strict minimum -> rank 0 always.
// Emit ranks 1..16. (Proven R8 kernel + batch argument.)
__global__ __launch_bounds__(512) void knn_kernel(const float* __restrict__ xyz, int b) {
    extern __shared__ float4 sh[];                 // 4096 * 16B = 64KB
    const unsigned FULL = 0xffffffffu;
    const int qbase = blockIdx.x * 32;             // 128 blocks per batch
    const int tid = threadIdx.x;
    const int w = tid >> 5, lane = tid & 31;
    const float* xb = xyz + (size_t)b * 3 * NN;

    for (int i = tid; i < NN; i += 512) {
        float x = xb[i], y = xb[NN + i], z = xb[2 * NN + i];
        float sq = fmaf(z, z, fmaf(y, y, x * x));
        sh[i] = make_float4(x, y, z, sq);
    }
    __syncthreads();

    const int qAi = qbase + 2 * w;
    const int qBi = qAi + 1;
    const float4 qA = sh[qAi];
    const float4 qB = sh[qBi];

    // ---- t = 0: evaluate first 32 candidates for both queries ----
    float dlA, dlB;
    int   ilA = lane, ilB = lane;
    {
        float4 c = sh[lane];
        dlA = fmaf(-2.0f, fmaf(qA.z, c.z, fmaf(qA.y, c.y, qA.x * c.x)), c.w);
        dlB = fmaf(-2.0f, fmaf(qB.z, c.z, fmaf(qB.y, c.y, qB.x * c.x)), c.w);
    }
    // fused bitonic sort across lanes for both lists (asc by dist, idx tie-break)
#pragma unroll
    for (int k = 2; k <= 32; k <<= 1) {
#pragma unroll
        for (int j = k >> 1; j > 0; j >>= 1) {
            float odA = __shfl_xor_sync(FULL, dlA, j);
            int   oiA = __shfl_xor_sync(FULL, ilA, j);
            float odB = __shfl_xor_sync(FULL, dlB, j);
            int   oiB = __shfl_xor_sync(FULL, ilB, j);
            bool keepLt = (((lane & k) == 0) == ((lane & j) == 0));
            bool ltA = (odA < dlA) || (odA == dlA && oiA < ilA);
            bool ltB = (odB < dlB) || (odB == dlB && oiB < ilB);
            bool swA = keepLt ? ltA : !ltA;
            bool swB = keepLt ? ltB : !ltB;
            if (swA) { dlA = odA; ilA = oiA; }
            if (swB) { dlB = odB; ilB = oiB; }
        }
    }
    float kthA = __shfl_sync(FULL, dlA, 16);   // 17th smallest
    float kthB = __shfl_sync(FULL, dlB, 16);

    // ---- main scan: one LDS per candidate serves both queries ----
#pragma unroll 2
    for (int t = 1; t < NN / 32; ++t) {
        const float4 c = sh[t * 32 + lane];
        float dA = fmaf(-2.0f, fmaf(qA.z, c.z, fmaf(qA.y, c.y, qA.x * c.x)), c.w);
        float dB = fmaf(-2.0f, fmaf(qB.z, c.z, fmaf(qB.y, c.y, qB.x * c.x)), c.w);

        unsigned mA = __ballot_sync(FULL, dA < kthA);
        unsigned mB = __ballot_sync(FULL, dB < kthB);
        if (mA) {
            do {
                const int src = __ffs(mA) - 1;
                mA &= mA - 1;
                const float dc = __shfl_sync(FULL, dA, src);
                const int   mc = t * 32 + src;
                const float up_d = __shfl_up_sync(FULL, dlA, 1);
                const int   up_i = __shfl_up_sync(FULL, ilA, 1);
                const bool here = dc < dlA;                 // strict: stable tie-break
                const bool prev = (lane > 0) && (dc < up_d);
                dlA = here ? (prev ? up_d : dc) : dlA;
                ilA = here ? (prev ? up_i : mc) : ilA;
            } while (mA);
            kthA = __shfl_sync(FULL, dlA, 16);
        }
        if (mB) {
            do {
                const int src = __ffs(mB) - 1;
                mB &= mB - 1;
                const float dc = __shfl_sync(FULL, dB, src);
                const int   mc = t * 32 + src;
                const float up_d = __shfl_up_sync(FULL, dlB, 1);
                const int   up_i = __shfl_up_sync(FULL, ilB, 1);
                const bool here = dc < dlB;
                const bool prev = (lane > 0) && (dc < up_d);
                dlB = here ? (prev ? up_d : dc) : dlB;
                ilB = here ? (prev ? up_i : mc) : ilB;
            } while (mB);
            kthB = __shfl_sync(FULL, dlB, 16);
        }
    }

    // ranks 1..16 (rank 0 == self)
    if (lane >= 1 && lane <= KK1) {
        g_idx[((size_t)b * NN + qAi) * KK1 + (lane - 1)] = ilA;
        g_idx[((size_t)b * NN + qBi) * KK1 + (lane - 1)] = ilB;
    }
}

// ---------------- SGEMM (per batch): BM=128 x BN=64, 8x4 micro-tile, f32x2 -------------
// grid (64, 4) = 256 blocks/batch -> chip stays full at per-batch granularity.
__global__ __launch_bounds__(256) void gemm_kernel(const float* __restrict__ xyz,
                                                   const float* __restrict__ feature,
                                                   int b) {
    __shared__ __align__(16) float As[16][128];
    __shared__ __align__(16) float Bs[16][64];

    const int tid = threadIdx.x;
    const int tr = tid >> 4;                       // 16 row-groups x 8 rows
    const int tc = tid & 15;                       // 16 col-groups x 4 points
    const int nl = blockIdx.x * 64;                // 64 point-tiles per batch
    const int rowbase = blockIdx.y * 128;          // 4 row-tiles

    const int la_k = tid >> 4;
    const int la_r = (tid & 15) * 8;
    const int lb_k = tid >> 4;
    const int lb_j = (tid & 15) * 4;

    u64 acc[8][2];
#pragma unroll
    for (int i = 0; i < 8; ++i) { acc[i][0] = 0ull; acc[i][1] = 0ull; }

    float4 pa0, pa1, pb0;
    {
        const float* srcA = g_WcT + la_k * RWS + rowbase + la_r;
        pa0 = *(const float4*)srcA; pa1 = *(const float4*)(srcA + 4);
        int kg = lb_k;
        const float* row = (kg < 3) ? (xyz + ((size_t)b * 3 + kg) * NN)
                                    : (feature + ((size_t)b * CC + (kg - 3)) * NN);
        pb0 = *(const float4*)(row + nl + lb_j);
    }

    for (int kt = 0; kt < KPAD / 16; ++kt) {
        *(float4*)&As[la_k][la_r]     = pa0;
        *(float4*)&As[la_k][la_r + 4] = pa1;
        *(float4*)&Bs[lb_k][lb_j]     = pb0;
        __syncthreads();
        if (kt + 1 < KPAD / 16) {
            const float* srcA = g_WcT + ((kt + 1) * 16 + la_k) * RWS + rowbase + la_r;
            pa0 = *(const float4*)srcA; pa1 = *(const float4*)(srcA + 4);
            int kg = (kt + 1) * 16 + lb_k;
            if (kg < KDIM) {
                const float* row = (kg < 3) ? (xyz + ((size_t)b * 3 + kg) * NN)
                                            : (feature + ((size_t)b * CC + (kg - 3)) * NN);
                pb0 = *(const float4*)(row + nl + lb_j);
            } else {
                pb0 = make_float4(0.f, 0.f, 0.f, 0.f);
            }
        }
#pragma unroll
        for (int k = 0; k < 16; ++k) {
            float4 a0 = *(const float4*)&As[k][tr * 8];
            float4 a1 = *(const float4*)&As[k][tr * 8 + 4];
            ulonglong2 bb2 = *(const ulonglong2*)&Bs[k][tc * 4];
            u64 bp0 = bb2.x, bp1 = bb2.y;
            float ar[8] = {a0.x, a0.y, a0.z, a0.w, a1.x, a1.y, a1.z, a1.w};
#pragma unroll
            for (int i = 0; i < 8; ++i) {
                u64 a2 = dup2(ar[i]);
                acc[i][0] = ffma2(a2, bp0, acc[i][0]);
                acc[i][1] = ffma2(a2, bp1, acc[i][1]);
            }
        }
        __syncthreads();
    }

    const int gr = rowbase + tr * 8;
    float bias[8];
#pragma unroll
    for (int i = 0; i < 8; ++i) bias[i] = g_bias[gr + i];
    float r_[8][4];
#pragma unroll
    for (int i = 0; i < 8; ++i) {
        unpack2(acc[i][0], r_[i][0], r_[i][1]);
        unpack2(acc[i][1], r_[i][2], r_[i][3]);
    }
#pragma unroll
    for (int j = 0; j < 4; ++j) {
        int p = b * NN + nl + tc * 4 + j;
        float* dst = g_P + (size_t)p * RWS + gr;
        float4 v0 = make_float4(r_[0][j] + bias[0], r_[1][j] + bias[1],
                                r_[2][j] + bias[2], r_[3][j] + bias[3]);
        float4 v1 = make_float4(r_[4][j] + bias[4], r_[5][j] + bias[5],
                                r_[6][j] + bias[6], r_[7][j] + bias[7]);
        *(float4*)dst       = v0;
        *(float4*)(dst + 4) = v1;
    }
}

// ---------------- attention (per batch) ----------------
#define WARP_FLOATS 1632
#define SM_RES      (8*WARP_FLOATS)
#define SM_ATTN_TOT (SM_RES + 8*132)

__global__ __launch_bounds__(256, 3) void attn_kernel(const float* __restrict__ feature,
                                                      const float* __restrict__ b1,
                                                      float* __restrict__ out,
                                                      int bb) {
    extern __shared__ __align__(16) float sm[];
    const int tid = threadIdx.x;
    const int w = tid >> 5, l = tid & 31;
    float* qw   = sm + w * WARP_FLOATS;
    float* kw   = qw + 8 * 68;
    float* resT = sm + SM_RES;

    const int lp = blockIdx.x * 8 + w;             // 512 blocks per batch
    const int gp = (bb << 12) + lp;
    const int* ip = g_idx + (size_t)gp * KK1;
    const float* Pbase = g_P + ((size_t)(bb << 12)) * RWS;
    const float* Sp    = g_P + (size_t)gp * RWS + 256;

    int c[16];
    {
        int4 t0 = ((const int4*)ip)[0]; int4 t1 = ((const int4*)ip)[1];
        int4 t2 = ((const int4*)ip)[2]; int4 t3 = ((const int4*)ip)[3];
        c[0]=t0.x; c[1]=t0.y; c[2]=t0.z; c[3]=t0.w;
        c[4]=t1.x; c[5]=t1.y; c[6]=t1.z; c[7]=t1.w;
        c[8]=t2.x; c[9]=t2.y; c[10]=t2.z; c[11]=t2.w;
        c[12]=t3.x; c[13]=t3.y; c[14]=t3.z; c[15]=t3.w;
    }

    // ---- gather q = Pq[c] + Sq ----
    {
        int a = l >> 2, qt = l & 3;
        const float4* src = (const float4*)(Pbase + (size_t)c[a] * RWS) + qt * 4;
        const float4* s4  = (const float4*)Sp + qt * 4;
        float4* dst = (float4*)(qw + a * 68 + qt * 16);
#pragma unroll
        for (int f = 0; f < 4; ++f) {
            float4 p = src[f], s = s4[f];
            dst[f] = make_float4(p.x + s.x, p.y + s.y, p.z + s.z, p.w + s.w);
        }
    }
    // ---- gather k = Pk[c] + Sk ----
    {
        int j = l >> 1, h = l & 1;
        const float4* src = (const float4*)(Pbase + (size_t)c[j] * RWS + 64 + h * 32);
        const float4* s4  = (const float4*)(Sp + 64 + h * 32);
        float4* dst = (float4*)(kw + j * 68 + h * 32);
#pragma unroll
        for (int f = 0; f < 8; ++f) {
            float4 p = src[f], s = s4[f];
            dst[f] = make_float4(p.x + s.x, p.y + s.y, p.z + s.z, p.w + s.w);
        }
    }
    __syncwarp();

    // ---- logits with packed f32x2 ----
    const int nq = l & 7, jg = l >> 3;
    u64 acc2[4] = {0ull, 0ull, 0ull, 0ull};
    const ulonglong2* qrow = (const ulonglong2*)(qw + nq * 68);
#pragma unroll
    for (int dc = 0; dc < 4; ++dc) {
        ulonglong2 qa = qrow[dc * 4 + 0], qb = qrow[dc * 4 + 1];
        ulonglong2 qc = qrow[dc * 4 + 2], qd = qrow[dc * 4 + 3];
#pragma unroll
        for (int j4 = 0; j4 < 4; ++j4) {
            const ulonglong2* kr = (const ulonglong2*)(kw + (j4 * 4 + jg) * 68);
            ulonglong2 ka = kr[dc * 4 + 0], kb = kr[dc * 4 + 1];
            ulonglong2 kc = kr[dc * 4 + 2], kd = kr[dc * 4 + 3];
            u64 s = acc2[j4];
            s = ffma2(qa.x, ka.x, s); s = ffma2(qa.y, ka.y, s);
            s = ffma2(qb.x, kb.x, s); s = ffma2(qb.y, kb.y, s);
            s = ffma2(qc.x, kc.x, s); s = ffma2(qc.y, kc.y, s);
            s = ffma2(qd.x, kd.x, s); s = ffma2(qd.y, kd.y, s);
            acc2[j4] = s;
        }
    }
    float acc[4];
#pragma unroll
    for (int j4 = 0; j4 < 4; ++j4) {
        float lo, hi; unpack2(acc2[j4], lo, hi);
        acc[j4] = lo + hi;
    }

    // ---- softmax over j per query row nq ----
    float mx = fmaxf(fmaxf(acc[0], acc[1]), fmaxf(acc[2], acc[3]));
    mx = fmaxf(mx, __shfl_xor_sync(0xffffffffu, mx, 8));
    mx = fmaxf(mx, __shfl_xor_sync(0xffffffffu, mx, 16));
    float e[4], ssum = 0.f;
#pragma unroll
    for (int j4 = 0; j4 < 4; ++j4) { e[j4] = __expf(acc[j4] - mx); ssum += e[j4]; }
    ssum += __shfl_xor_sync(0xffffffffu, ssum, 8);
    ssum += __shfl_xor_sync(0xffffffffu, ssum, 16);
    float inv = 1.0f / ssum;
    float wj[4];
#pragma unroll
    for (int j4 = 0; j4 < 4; ++j4) wj[j4] = e[j4] * inv;

    // ---- colsum over the 8 queries ----
#pragma unroll
    for (int off = 1; off < 8; off <<= 1)
#pragma unroll
        for (int j4 = 0; j4 < 4; ++j4)
            wj[j4] += __shfl_xor_sync(0xffffffffu, wj[j4], off);

    // ---- res128 = sum_j w[j]*PvProj[c_j] + wsum*SvProj (packed) ----
    u64 av0 = 0ull, av1 = 0ull;
#pragma unroll
    for (int j = 0; j < 16; ++j) {
        float wjv = __shfl_sync(0xffffffffu, wj[j >> 2], (j & 3) * 8);
        u64 w2 = dup2(wjv);
        ulonglong2 vv = *(const ulonglong2*)(Pbase + (size_t)c[j] * RWS + 128 + 4 * l);
        av0 = ffma2(w2, vv.x, av0);
        av1 = ffma2(w2, vv.y, av1);
    }
    float wsum = wj[0] + wj[1] + wj[2] + wj[3];
    wsum += __shfl_xor_sync(0xffffffffu, wsum, 8);
    wsum += __shfl_xor_sync(0xffffffffu, wsum, 16);
    {
        u64 w2 = dup2(wsum);
        ulonglong2 sv = *(const ulonglong2*)(Sp + 128 + 4 * l);
        av0 = ffma2(w2, sv.x, av0);
        av1 = ffma2(w2, sv.y, av1);
    }
    {
        float4 r;
        unpack2(av0, r.x, r.y);
        unpack2(av1, r.z, r.w);
        *(float4*)(resT + w * 132 + 4 * l) = r;
    }
    __syncthreads();

    // ---- out = res + b1 + feature ----
    const int o  = tid >> 1;
    const int pg = (tid & 1) * 4;
    const int nl = blockIdx.x * 8;
    size_t base = ((size_t)bb * CC + o) * NN + nl + pg;
    float bo = b1[o];
    float4 fv = *(const float4*)(feature + base);
    float4 ov;
    ov.x = resT[(pg + 0) * 132 + o] + bo + fv.x;
    ov.y = resT[(pg + 1) * 132 + o] + bo + fv.y;
    ov.z = resT[(pg + 2) * 132 + o] + bo + fv.z;
    ov.w = resT[(pg + 3) * 132 + o] + bo + fv.w;
    *(float4*)(out + base) = ov;
}

// ---------------- launch: per-batch pipeline, chip-filling chunks ----------------
extern "C" void kernel_launch(void* const* d_in, const int* in_sizes, int n_in,
                              void* d_out, int out_size) {
    const float* feature = (const float*)d_in[0];
    const float* xyz     = (const float*)d_in[1];
    const float* wq      = (const float*)d_in[2];
    const float* bq      = (const float*)d_in[3];
    const float* wk      = (const float*)d_in[4];
    const float* bk      = (const float*)d_in[5];
    const float* wv      = (const float*)d_in[6];
    const float* bv      = (const float*)d_in[7];
    const float* w1      = (const float*)d_in[8];
    const float* b1      = (const float*)d_in[9];
    float* out = (float*)d_out;

    static cudaStream_t s_aux = []{
        cudaStream_t s; cudaStreamCreateWithFlags(&s, cudaStreamNonBlocking); return s; }();
    static cudaStream_t s_attn = []{
        cudaStream_t s; cudaStreamCreateWithFlags(&s, cudaStreamNonBlocking); return s; }();
    static cudaEvent_t ev_fork = []{
        cudaEvent_t e; cudaEventCreateWithFlags(&e, cudaEventDisableTiming); return e; }();
    static cudaEvent_t ev_done = []{
        cudaEvent_t e; cudaEventCreateWithFlags(&e, cudaEventDisableTiming); return e; }();
    static cudaEvent_t ev_knn[BB] = {};
    static cudaEvent_t ev_gemm[BB] = {};
    static bool init_done = []{
        for (int b = 0; b < BB; ++b) {
            cudaEventCreateWithFlags(&ev_knn[b],  cudaEventDisableTiming);
            cudaEventCreateWithFlags(&ev_gemm[b], cudaEventDisableTiming);
        }
        cudaFuncSetAttribute(knn_kernel,  cudaFuncAttributeMaxDynamicSharedMemorySize, NN * 16);
        cudaFuncSetAttribute(attn_kernel, cudaFuncAttributeMaxDynamicSharedMemorySize, SM_ATTN_TOT * 4);
        return true; }();
    (void)init_done;

    const int knn_smem  = NN * 16;
    const int attn_smem = SM_ATTN_TOT * 4;

    cudaEventRecord(ev_fork, 0);
    cudaStreamWaitEvent(s_aux, ev_fork, 0);

    // aux: prep -> gemm per batch (256 chip-filling blocks each)
    {
        int total = KPAD * RWS + RWS;
        prep_kernel<<<(total + 255) / 256, 256, 0, s_aux>>>(wq, wk, wv, bq, bk, bv, w1);
    }
    for (int b = 0; b < BB; ++b) {
        gemm_kernel<<<dim3(NN / 64, RWS / 128), 256, 0, s_aux>>>(xyz, feature, b);
        cudaEventRecord(ev_gemm[b], s_aux);
    }

    // main: knn per batch (128 blocks x 512 threads each)
    for (int b = 0; b < BB; ++b) {
        knn_kernel<<<128, 512, knn_smem>>>(xyz, b);
        cudaEventRecord(ev_knn[b], 0);
    }

    // attn stream: fire each batch as soon as its knn + gemm are done
    for (int b = 0; b < BB; ++b) {
        cudaStreamWaitEvent(s_attn, ev_knn[b], 0);
        cudaStreamWaitEvent(s_attn, ev_gemm[b], 0);
        attn_kernel<<<NN / 8, 256, attn_smem, s_attn>>>(feature, b1, out, b);
    }

    cudaEventRecord(ev_done, s_attn);
    cudaStreamWaitEvent(0, ev_done, 0);
}

// round 14
// speedup vs baseline: 1.3187x; 1.1208x over previous
#include <cuda_runtime.h>
#include <math.h>

#define BB   4
#define NN   4096
#define CC   128
#define KK1  16
#define KK2  8
#define TDD  64
#define KDIM 131
#define KPAD 144
#define RWS  512
#define NPTS (BB*NN)

typedef unsigned long long u64;

__device__ __forceinline__ u64 ffma2(u64 a, u64 b, u64 c) {
    u64 d;
    asm("fma.rn.f32x2 %0, %1, %2, %3;" : "=l"(d) : "l"(a), "l"(b), "l"(c));
    return d;
}
__device__ __forceinline__ u64 dup2(float x) {
    u64 d;
    asm("mov.b64 %0, {%1, %1};" : "=l"(d) : "r"(__float_as_int(x)));
    return d;
}
__device__ __forceinline__ void unpack2(u64 v, float& lo, float& hi) {
    int a, b;
    asm("mov.b64 {%0, %1}, %2;" : "=r"(a), "=r"(b) : "l"(v));
    lo = __int_as_float(a); hi = __int_as_float(b);
}

// ---------------- scratch ----------------
__device__ int   g_idx[NPTS*KK1];
// per point rows: [0:64)Pq [64:128)Pk [128:256)PvProj [256:320)Sq [320:384)Sk [384:512)SvProj
__device__ float g_P[(size_t)NPTS*RWS];
__device__ float g_WcT[KPAD*RWS];
__device__ float g_bias[RWS];

// ---------------- prep ----------------
__global__ void prep_kernel(const float* __restrict__ wq, const float* __restrict__ wk,
                            const float* __restrict__ wv, const float* __restrict__ bq,
                            const float* __restrict__ bk, const float* __restrict__ bv,
                            const float* __restrict__ w1) {
    int i = blockIdx.x * blockDim.x + threadIdx.x;
    const int total1 = KPAD * RWS;
    if (i < total1) {
        int k = i >> 9;
        int r = i & 511;
        float val = 0.f;
        if (k < KDIM) {
            if (r < 128) {                       // Pq | Pk
                const float* w = (r < 64) ? wq : wk;
                const float* row = w + (r & 63) * 262;
                val = (k < 3) ? row[k] : row[6 + (k - 3)];
            } else if (r < 256) {                // PvProj = w1 @ Pv
                int o = r - 128;
                float s = 0.f;
                for (int m = 0; m < TDD; ++m) {
                    const float* row = wv + m * 262;
                    float wvk = (k < 3) ? row[k] : row[6 + (k - 3)];
                    s = fmaf(w1[o * TDD + m], wvk, s);
                }
                val = s;
            } else if (r < 384) {                // Sq | Sk
                const float* w = (r < 320) ? wq : wk;
                const float* row = w + (r & 63) * 262;
                val = (k < 3) ? (row[3 + k] - row[k])
                              : (row[134 + (k - 3)] - row[6 + (k - 3)]);
            } else {                             // SvProj = w1 @ Sv
                int o = r - 384;
                float s = 0.f;
                for (int m = 0; m < TDD; ++m) {
                    const float* row = wv + m * 262;
                    float d = (k < 3) ? (row[3 + k] - row[k])
                                      : (row[134 + (k - 3)] - row[6 + (k - 3)]);
                    s = fmaf(w1[o * TDD + m], d, s);
                }
                val = s;
            }
        }
        g_WcT[(k << 9) + r] = val;
        return;
    }
    i -= total1;
    if (i < RWS) {
        float bval = 0.f;
        if (i >= 256 && i < 320) bval = bq[i - 256];
        else if (i >= 320 && i < 384) bval = bk[i - 320];
        else if (i >= 384) {
            int o = i - 384;
            float s = 0.f;
            for (int m = 0; m < TDD; ++m) s = fmaf(w1[o * TDD + m], bv[m], s);
            bval = s;
        }
        g_bias[i] = bval;
    }
}

// ---------------- FUSED: gemm blocks (even) + knn blocks (odd) in ONE grid ----------------
// Forces per-SM co-residency of fma-bound gemm and issue/MIO-bound knn so their
// idle issue slots interleave (stream-level forks proved to serialize, R10-R12).
__global__ __launch_bounds__(256, 3) void fused_kernel(const float* __restrict__ xyz,
                                                       const float* __restrict__ feature) {
    extern __shared__ __align__(16) float smraw[];
    const int role = blockIdx.x & 1;
    const int gi   = blockIdx.x >> 1;              // 0..1023 within role
    const int tid  = threadIdx.x;

    if (role == 0) {
        // ================= GEMM role: BM=128 x BN=64, 8x4 micro-tile, f32x2 ============
        float* As = smraw;                         // [16][128]
        float* Bs = smraw + 16 * 128;              // [16][64]

        const int tr = tid >> 4;
        const int tc = tid & 15;
        const int pt = gi & 255;                   // 256 point-tiles (global)
        const int rt = gi >> 8;                    // 4 row-tiles
        const int p0 = pt * 64;
        const int b  = p0 >> 12;
        const int nl = p0 & (NN - 1);
        const int rowbase = rt * 128;

        const int la_k = tid >> 4;
        const int la_r = (tid & 15) * 8;
        const int lb_k = tid >> 4;
        const int lb_j = (tid & 15) * 4;

        u64 acc[8][2];
#pragma unroll
        for (int i = 0; i < 8; ++i) { acc[i][0] = 0ull; acc[i][1] = 0ull; }

        float4 pa0, pa1, pb0;
        {
            const float* srcA = g_WcT + la_k * RWS + rowbase + la_r;
            pa0 = *(const float4*)srcA; pa1 = *(const float4*)(srcA + 4);
            int kg = lb_k;
            const float* row = (kg < 3) ? (xyz + ((size_t)b * 3 + kg) * NN)
                                        : (feature + ((size_t)b * CC + (kg - 3)) * NN);
            pb0 = *(const float4*)(row + nl + lb_j);
        }

        for (int kt = 0; kt < KPAD / 16; ++kt) {
            *(float4*)&As[la_k * 128 + la_r]     = pa0;
            *(float4*)&As[la_k * 128 + la_r + 4] = pa1;
            *(float4*)&Bs[lb_k * 64 + lb_j]      = pb0;
            __syncthreads();
            if (kt + 1 < KPAD / 16) {
                const float* srcA = g_WcT + ((kt + 1) * 16 + la_k) * RWS + rowbase + la_r;
                pa0 = *(const float4*)srcA; pa1 = *(const float4*)(srcA + 4);
                int kg = (kt + 1) * 16 + lb_k;
                if (kg < KDIM) {
                    const float* row = (kg < 3) ? (xyz + ((size_t)b * 3 + kg) * NN)
                                                : (feature + ((size_t)b * CC + (kg - 3)) * NN);
                    pb0 = *(const float4*)(row + nl + lb_j);
                } else {
                    pb0 = make_float4(0.f, 0.f, 0.f, 0.f);
                }
            }
#pragma unroll
            for (int k = 0; k < 16; ++k) {
                float4 a0 = *(const float4*)&As[k * 128 + tr * 8];
                float4 a1 = *(const float4*)&As[k * 128 + tr * 8 + 4];
                ulonglong2 bb2 = *(const ulonglong2*)&Bs[k * 64 + tc * 4];
                u64 bp0 = bb2.x, bp1 = bb2.y;
                float ar[8] = {a0.x, a0.y, a0.z, a0.w, a1.x, a1.y, a1.z, a1.w};
#pragma unroll
                for (int i = 0; i < 8; ++i) {
                    u64 a2 = dup2(ar[i]);
                    acc[i][0] = ffma2(a2, bp0, acc[i][0]);
                    acc[i][1] = ffma2(a2, bp1, acc[i][1]);
                }
            }
            __syncthreads();
        }

        const int gr = rowbase + tr * 8;
        float bias[8];
#pragma unroll
        for (int i = 0; i < 8; ++i) bias[i] = g_bias[gr + i];
        float r_[8][4];
#pragma unroll
        for (int i = 0; i < 8; ++i) {
            unpack2(acc[i][0], r_[i][0], r_[i][1]);
            unpack2(acc[i][1], r_[i][2], r_[i][3]);
        }
#pragma unroll
        for (int j = 0; j < 4; ++j) {
            int p = p0 + tc * 4 + j;
            float* dst = g_P + (size_t)p * RWS + gr;
            float4 v0 = make_float4(r_[0][j] + bias[0], r_[1][j] + bias[1],
                                    r_[2][j] + bias[2], r_[3][j] + bias[3]);
            float4 v1 = make_float4(r_[4][j] + bias[4], r_[5][j] + bias[5],
                                    r_[6][j] + bias[6], r_[7][j] + bias[7]);
            *(float4*)dst       = v0;
            *(float4*)(dst + 4) = v1;
        }
    } else {
        // ================= kNN role: warp per 2 queries, smem tile, top-17 =============
        // Self not excluded: d(self) = -|q|^2 is the strict minimum -> rank 0 always;
        // emit ranks 1..16 (== reference dropping idx[...,0]).
        float4* sh = (float4*)smraw;               // 4096 * 16B = 64KB
        const unsigned FULL = 0xffffffffu;
        const int b = gi >> 8;                     // 256 knn blocks per batch
        const int qbase = (gi & 255) * 16;         // 16 queries per block (8 warps)
        const int w = tid >> 5, lane = tid & 31;
        const float* xb = xyz + (size_t)b * 3 * NN;

        for (int i = tid; i < NN; i += 256) {
            float x = xb[i], y = xb[NN + i], z = xb[2 * NN + i];
            float sq = fmaf(z, z, fmaf(y, y, x * x));
            sh[i] = make_float4(x, y, z, sq);
        }
        __syncthreads();

        const int qAi = qbase + 2 * w;
        const int qBi = qAi + 1;
        const float4 qA = sh[qAi];
        const float4 qB = sh[qBi];

        float dlA, dlB;
        int   ilA = lane, ilB = lane;
        {
            float4 c = sh[lane];
            dlA = fmaf(-2.0f, fmaf(qA.z, c.z, fmaf(qA.y, c.y, qA.x * c.x)), c.w);
            dlB = fmaf(-2.0f, fmaf(qB.z, c.z, fmaf(qB.y, c.y, qB.x * c.x)), c.w);
        }
#pragma unroll
        for (int k = 2; k <= 32; k <<= 1) {
#pragma unroll
            for (int j = k >> 1; j > 0; j >>= 1) {
                float odA = __shfl_xor_sync(FULL, dlA, j);
                int   oiA = __shfl_xor_sync(FULL, ilA, j);
                float odB = __shfl_xor_sync(FULL, dlB, j);
                int   oiB = __shfl_xor_sync(FULL, ilB, j);
                bool keepLt = (((lane & k) == 0) == ((lane & j) == 0));
                bool ltA = (odA < dlA) || (odA == dlA && oiA < ilA);
                bool ltB = (odB < dlB) || (odB == dlB && oiB < ilB);
                bool swA = keepLt ? ltA : !ltA;
                bool swB = keepLt ? ltB : !ltB;
                if (swA) { dlA = odA; ilA = oiA; }
                if (swB) { dlB = odB; ilB = oiB; }
            }
        }
        float kthA = __shfl_sync(FULL, dlA, 16);   // 17th smallest
        float kthB = __shfl_sync(FULL, dlB, 16);

#pragma unroll 2
        for (int t = 1; t < NN / 32; ++t) {
            const float4 c = sh[t * 32 + lane];
            float dA = fmaf(-2.0f, fmaf(qA.z, c.z, fmaf(qA.y, c.y, qA.x * c.x)), c.w);
            float dB = fmaf(-2.0f, fmaf(qB.z, c.z, fmaf(qB.y, c.y, qB.x * c.x)), c.w);

            unsigned mA = __ballot_sync(FULL, dA < kthA);
            unsigned mB = __ballot_sync(FULL, dB < kthB);
            if (mA) {
                do {
                    const int src = __ffs(mA) - 1;
                    mA &= mA - 1;
                    const float dc = __shfl_sync(FULL, dA, src);
                    const int   mc = t * 32 + src;
                    const float up_d = __shfl_up_sync(FULL, dlA, 1);
                    const int   up_i = __shfl_up_sync(FULL, ilA, 1);
                    const bool here = dc < dlA;             // strict: stable tie-break
                    const bool prev = (lane > 0) && (dc < up_d);
                    dlA = here ? (prev ? up_d : dc) : dlA;
                    ilA = here ? (prev ? up_i : mc) : ilA;
                } while (mA);
                kthA = __shfl_sync(FULL, dlA, 16);
            }
            if (mB) {
                do {
                    const int src = __ffs(mB) - 1;
                    mB &= mB - 1;
                    const float dc = __shfl_sync(FULL, dB, src);
                    const int   mc = t * 32 + src;
                    const float up_d = __shfl_up_sync(FULL, dlB, 1);
                    const int   up_i = __shfl_up_sync(FULL, ilB, 1);
                    const bool here = dc < dlB;
                    const bool prev = (lane > 0) && (dc < up_d);
                    dlB = here ? (prev ? up_d : dc) : dlB;
                    ilB = here ? (prev ? up_i : mc) : ilB;
                } while (mB);
                kthB = __shfl_sync(FULL, dlB, 16);
            }
        }

        if (lane >= 1 && lane <= KK1) {
            g_idx[((size_t)b * NN + qAi) * KK1 + (lane - 1)] = ilA;
            g_idx[((size_t)b * NN + qBi) * KK1 + (lane - 1)] = ilB;
        }
    }
}

// ---------------- attention (whole grid) ----------------
#define WARP_FLOATS 1632
#define SM_RES      (8*WARP_FLOATS)
#define SM_ATTN_TOT (SM_RES + 8*132)

__global__ __launch_bounds__(256, 3) void attn_kernel(const float* __restrict__ feature,
                                                      const float* __restrict__ b1,
                                                      float* __restrict__ out) {
    extern __shared__ __align__(16) float sm[];
    const int tid = threadIdx.x;
    const int w = tid >> 5, l = tid & 31;
    float* qw   = sm + w * WARP_FLOATS;
    float* kw   = qw + 8 * 68;
    float* resT = sm + SM_RES;

    const int gp = blockIdx.x * 8 + w;
    const int b  = gp >> 12;
    const int* ip = g_idx + (size_t)gp * KK1;
    const float* Pbase = g_P + ((size_t)(b << 12)) * RWS;
    const float* Sp    = g_P + (size_t)gp * RWS + 256;

    int c[16];
    {
        int4 t0 = ((const int4*)ip)[0]; int4 t1 = ((const int4*)ip)[1];
        int4 t2 = ((const int4*)ip)[2]; int4 t3 = ((const int4*)ip)[3];
        c[0]=t0.x; c[1]=t0.y; c[2]=t0.z; c[3]=t0.w;
        c[4]=t1.x; c[5]=t1.y; c[6]=t1.z; c[7]=t1.w;
        c[8]=t2.x; c[9]=t2.y; c[10]=t2.z; c[11]=t2.w;
        c[12]=t3.x; c[13]=t3.y; c[14]=t3.z; c[15]=t3.w;
    }

    // ---- gather q = Pq[c] + Sq ----
    {
        int a = l >> 2, qt = l & 3;
        const float4* src = (const float4*)(Pbase + (size_t)c[a] * RWS) + qt * 4;
        const float4* s4  = (const float4*)Sp + qt * 4;
        float4* dst = (float4*)(qw + a * 68 + qt * 16);
#pragma unroll
        for (int f = 0; f < 4; ++f) {
            float4 p = src[f], s = s4[f];
            dst[f] = make_float4(p.x + s.x, p.y + s.y, p.z + s.z, p.w + s.w);
        }
    }
    // ---- gather k = Pk[c] + Sk ----
    {
        int j = l >> 1, h = l & 1;
        const float4* src = (const float4*)(Pbase + (size_t)c[j] * RWS + 64 + h * 32);
        const float4* s4  = (const float4*)(Sp + 64 + h * 32);
        float4* dst = (float4*)(kw + j * 68 + h * 32);
#pragma unroll
        for (int f = 0; f < 8; ++f) {
            float4 p = src[f], s = s4[f];
            dst[f] = make_float4(p.x + s.x, p.y + s.y, p.z + s.z, p.w + s.w);
        }
    }
    __syncwarp();

    // ---- logits with packed f32x2 ----
    const int nq = l & 7, jg = l >> 3;
    u64 acc2[4] = {0ull, 0ull, 0ull, 0ull};
    const ulonglong2* qrow = (const ulonglong2*)(qw + nq * 68);
#pragma unroll
    for (int dc = 0; dc < 4; ++dc) {
        ulonglong2 qa = qrow[dc * 4 + 0], qb = qrow[dc * 4 + 1];
        ulonglong2 qc = qrow[dc * 4 + 2], qd = qrow[dc * 4 + 3];
#pragma unroll
        for (int j4 = 0; j4 < 4; ++j4) {
            const ulonglong2* kr = (const ulonglong2*)(kw + (j4 * 4 + jg) * 68);
            ulonglong2 ka = kr[dc * 4 + 0], kb = kr[dc * 4 + 1];
            ulonglong2 kc = kr[dc * 4 + 2], kd = kr[dc * 4 + 3];
            u64 s = acc2[j4];
            s = ffma2(qa.x, ka.x, s); s = ffma2(qa.y, ka.y, s);
            s = ffma2(qb.x, kb.x, s); s = ffma2(qb.y, kb.y, s);
            s = ffma2(qc.x, kc.x, s); s = ffma2(qc.y, kc.y, s);
            s = ffma2(qd.x, kd.x, s); s = ffma2(qd.y, kd.y, s);
            acc2[j4] = s;
        }
    }
    float acc[4];
#pragma unroll
    for (int j4 = 0; j4 < 4; ++j4) {
        float lo, hi; unpack2(acc2[j4], lo, hi);
        acc[j4] = lo + hi;
    }

    // ---- softmax over j per query row nq ----
    float mx = fmaxf(fmaxf(acc[0], acc[1]), fmaxf(acc[2], acc[3]));
    mx = fmaxf(mx, __shfl_xor_sync(0xffffffffu, mx, 8));
    mx = fmaxf(mx, __shfl_xor_sync(0xffffffffu, mx, 16));
    float e[4], ssum = 0.f;
#pragma unroll
    for (int j4 = 0; j4 < 4; ++j4) { e[j4] = __expf(acc[j4] - mx); ssum += e[j4]; }
    ssum += __shfl_xor_sync(0xffffffffu, ssum, 8);
    ssum += __shfl_xor_sync(0xffffffffu, ssum, 16);
    float inv = 1.0f / ssum;
    float wj[4];
#pragma unroll
    for (int j4 = 0; j4 < 4; ++j4) wj[j4] = e[j4] * inv;

    // ---- colsum over the 8 queries ----
#pragma unroll
    for (int off = 1; off < 8; off <<= 1)
#pragma unroll
        for (int j4 = 0; j4 < 4; ++j4)
            wj[j4] += __shfl_xor_sync(0xffffffffu, wj[j4], off);

    // ---- res128 = sum_j w[j]*PvProj[c_j] + wsum*SvProj (packed) ----
    u64 av0 = 0ull, av1 = 0ull;
#pragma unroll
    for (int j = 0; j < 16; ++j) {
        float wjv = __shfl_sync(0xffffffffu, wj[j >> 2], (j & 3) * 8);
        u64 w2 = dup2(wjv);
        ulonglong2 vv = *(const ulonglong2*)(Pbase + (size_t)c[j] * RWS + 128 + 4 * l);
        av0 = ffma2(w2, vv.x, av0);
        av1 = ffma2(w2, vv.y, av1);
    }
    float wsum = wj[0] + wj[1] + wj[2] + wj[3];
    wsum += __shfl_xor_sync(0xffffffffu, wsum, 8);
    wsum += __shfl_xor_sync(0xffffffffu, wsum, 16);
    {
        u64 w2 = dup2(wsum);
        ulonglong2 sv = *(const ulonglong2*)(Sp + 128 + 4 * l);
        av0 = ffma2(w2, sv.x, av0);
        av1 = ffma2(w2, sv.y, av1);
    }
    {
        float4 r;
        unpack2(av0, r.x, r.y);
        unpack2(av1, r.z, r.w);
        *(float4*)(resT + w * 132 + 4 * l) = r;
    }
    __syncthreads();

    // ---- out = res + b1 + feature ----
    const int o  = tid >> 1;
    const int pg = (tid & 1) * 4;
    const int gp0 = blockIdx.x * 8;
    const int bb = gp0 >> 12, nl = gp0 & (NN - 1);
    size_t base = ((size_t)bb * CC + o) * NN + nl + pg;
    float bo = b1[o];
    float4 fv = *(const float4*)(feature + base);
    float4 ov;
    ov.x = resT[(pg + 0) * 132 + o] + bo + fv.x;
    ov.y = resT[(pg + 1) * 132 + o] + bo + fv.y;
    ov.z = resT[(pg + 2) * 132 + o] + bo + fv.z;
    ov.w = resT[(pg + 3) * 132 + o] + bo + fv.w;
    *(float4*)(out + base) = ov;
}

// ---------------- launch: plain serial, single stream ----------------
extern "C" void kernel_launch(void* const* d_in, const int* in_sizes, int n_in,
                              void* d_out, int out_size) {
    const float* feature = (const float*)d_in[0];
    const float* xyz     = (const float*)d_in[1];
    const float* wq      = (const float*)d_in[2];
    const float* bq      = (const float*)d_in[3];
    const float* wk      = (const float*)d_in[4];
    const float* bk      = (const float*)d_in[5];
    const float* wv      = (const float*)d_in[6];
    const float* bv      = (const float*)d_in[7];
    const float* w1      = (const float*)d_in[8];
    const float* b1      = (const float*)d_in[9];
    float* out = (float*)d_out;

    static bool attr_done = false;
    if (!attr_done) {
        cudaFuncSetAttribute(fused_kernel, cudaFuncAttributeMaxDynamicSharedMemorySize, NN * 16);
        cudaFuncSetAttribute(attn_kernel,  cudaFuncAttributeMaxDynamicSharedMemorySize, SM_ATTN_TOT * 4);
        attr_done = true;
    }

    const int fused_smem = NN * 16;                // 64KB (knn tile; gemm uses 12KB of it)
    const int attn_smem  = SM_ATTN_TOT * 4;

    {
        int total = KPAD * RWS + RWS;
        prep_kernel<<<(total + 255) / 256, 256>>>(wq, wk, wv, bq, bk, bv, w1);
    }
    // 2048 blocks: even = gemm tiles (1024), odd = knn blocks (1024) — interleaved
    // so every SM carries a mix of fma-bound and issue/MIO-bound work.
    fused_kernel<<<2048, 256, fused_smem>>>(xyz, feature);
    attn_kernel<<<NPTS / 8, 256, attn_smem>>>(feature, b1, out);
}

// round 15
// speedup vs baseline: 1.3219x; 1.0024x over previous
#include <cuda_runtime.h>
#include <math.h>

#define BB   4
#define NN   4096
#define CC   128
#define KK1  16
#define KK2  8
#define TDD  64
#define KDIM 131
#define KPAD 144
#define RWS  512
#define NPTS (BB*NN)

typedef unsigned long long u64;

__device__ __forceinline__ u64 ffma2(u64 a, u64 b, u64 c) {
    u64 d;
    asm("fma.rn.f32x2 %0, %1, %2, %3;" : "=l"(d) : "l"(a), "l"(b), "l"(c));
    return d;
}
__device__ __forceinline__ u64 dup2(float x) {
    u64 d;
    asm("mov.b64 %0, {%1, %1};" : "=l"(d) : "r"(__float_as_int(x)));
    return d;
}
__device__ __forceinline__ void unpack2(u64 v, float& lo, float& hi) {
    int a, b;
    asm("mov.b64 {%0, %1}, %2;" : "=r"(a), "=r"(b) : "l"(v));
    lo = __int_as_float(a); hi = __int_as_float(b);
}

// ---------------- scratch ----------------
__device__ int   g_idx[NPTS*KK1];
// per point rows: [0:64)Pq [64:128)Pk [128:256)PvProj [256:320)Sq [320:384)Sk [384:512)SvProj
__device__ float g_P[(size_t)NPTS*RWS];
__device__ float g_WcT[KPAD*RWS];
__device__ float g_bias[RWS];

// ---------------- prep: smem-tiled (one block per k-row; block 144 = bias) ----------------
__global__ __launch_bounds__(512) void prep_kernel(const float* __restrict__ wq,
                                                   const float* __restrict__ wk,
                                                   const float* __restrict__ wv,
                                                   const float* __restrict__ bq,
                                                   const float* __restrict__ bk,
                                                   const float* __restrict__ bv,
                                                   const float* __restrict__ w1) {
    __shared__ float w1s[CC * 65];                 // padded stride 65: conflict-free
    __shared__ float wvP[TDD];                     // wv[m][kmap]
    __shared__ float wvS[TDD];                     // wv diff column
    const int tid = threadIdx.x;
    const int k = blockIdx.x;

    // stage w1 into smem: w1[o][m] -> w1s[o*65+m]
    for (int i = tid; i < CC * TDD; i += 512) {
        int o = i >> 6, m = i & 63;
        w1s[o * 65 + m] = w1[i];
    }

    if (k < KPAD) {
        // stage wv columns
        if (tid < 2 * TDD) {
            int m = tid & 63;
            const float* row = wv + m * 262;
            if (k < KDIM) {
                float p = (k < 3) ? row[k] : row[6 + (k - 3)];
                float s = (k < 3) ? (row[3 + k] - row[k])
                                  : (row[134 + (k - 3)] - row[6 + (k - 3)]);
                if (tid < TDD) wvP[m] = p; else wvS[m] = s;
            } else {
                if (tid < TDD) wvP[m] = 0.f; else wvS[m] = 0.f;
            }
        }
        __syncthreads();

        const int r = tid;                         // 512 outputs per k
        float val = 0.f;
        if (k < KDIM) {
            if (r < 128) {                         // Pq | Pk
                const float* w = (r < 64) ? wq : wk;
                const float* row = w + (r & 63) * 262;
                val = (k < 3) ? row[k] : row[6 + (k - 3)];
            } else if (r < 256) {                  // PvProj = w1 @ Pv column
                const float* wr = w1s + (r - 128) * 65;
                float s = 0.f;
#pragma unroll 16
                for (int m = 0; m < TDD; ++m) s = fmaf(wr[m], wvP[m], s);
                val = s;
            } else if (r < 384) {                  // Sq | Sk
                const float* w = (r < 320) ? wq : wk;
                const float* row = w + (r & 63) * 262;
                val = (k < 3) ? (row[3 + k] - row[k])
                              : (row[134 + (k - 3)] - row[6 + (k - 3)]);
            } else {                               // SvProj = w1 @ Sv column
                const float* wr = w1s + (r - 384) * 65;
                float s = 0.f;
#pragma unroll 16
                for (int m = 0; m < TDD; ++m) s = fmaf(wr[m], wvS[m], s);
                val = s;
            }
        }
        g_WcT[(k << 9) + r] = val;
    } else {
        // bias block
        __syncthreads();
        const int i = tid;
        float bval = 0.f;
        if (i >= 256 && i < 320) bval = bq[i - 256];
        else if (i >= 320 && i < 384) bval = bk[i - 320];
        else if (i >= 384) {
            const float* wr = w1s + (i - 384) * 65;
            float s = 0.f;
#pragma unroll 16
            for (int m = 0; m < TDD; ++m) s = fmaf(wr[m], bv[m], s);
            bval = s;
        }
        g_bias[i] = bval;
    }
}

// ---------------- kNN: warp per 2 queries, smem tile, top-17 (R8 exact) ----------------
// Self is NOT excluded: d(self) = -|q|^2 is the strict minimum -> rank 0 always.
// Emit ranks 1..16 (== reference dropping idx[...,0]).
__global__ __launch_bounds__(512) void knn_kernel(const float* __restrict__ xyz) {
    extern __shared__ float4 sh[];                 // 4096 * 16B = 64KB
    const unsigned FULL = 0xffffffffu;
    const int b = blockIdx.x >> 7;                 // 128 blocks per batch
    const int qbase = (blockIdx.x & 127) * 32;     // 32 queries per block
    const int tid = threadIdx.x;
    const int w = tid >> 5, lane = tid & 31;
    const float* xb = xyz + (size_t)b * 3 * NN;

    for (int i = tid; i < NN; i += 512) {
        float x = xb[i], y = xb[NN + i], z = xb[2 * NN + i];
        float sq = fmaf(z, z, fmaf(y, y, x * x));
        sh[i] = make_float4(x, y, z, sq);
    }
    __syncthreads();

    const int qAi = qbase + 2 * w;
    const int qBi = qAi + 1;
    const float4 qA = sh[qAi];
    const float4 qB = sh[qBi];

    float dlA, dlB;
    int   ilA = lane, ilB = lane;
    {
        float4 c = sh[lane];
        dlA = fmaf(-2.0f, fmaf(qA.z, c.z, fmaf(qA.y, c.y, qA.x * c.x)), c.w);
        dlB = fmaf(-2.0f, fmaf(qB.z, c.z, fmaf(qB.y, c.y, qB.x * c.x)), c.w);
    }
#pragma unroll
    for (int k = 2; k <= 32; k <<= 1) {
#pragma unroll
        for (int j = k >> 1; j > 0; j >>= 1) {
            float odA = __shfl_xor_sync(FULL, dlA, j);
            int   oiA = __shfl_xor_sync(FULL, ilA, j);
            float odB = __shfl_xor_sync(FULL, dlB, j);
            int   oiB = __shfl_xor_sync(FULL, ilB, j);
            bool keepLt = (((lane & k) == 0) == ((lane & j) == 0));
            bool ltA = (odA < dlA) || (odA == dlA && oiA < ilA);
            bool ltB = (odB < dlB) || (odB == dlB && oiB < ilB);
            bool swA = keepLt ? ltA : !ltA;
            bool swB = keepLt ? ltB : !ltB;
            if (swA) { dlA = odA; ilA = oiA; }
            if (swB) { dlB = odB; ilB = oiB; }
        }
    }
    float kthA = __shfl_sync(FULL, dlA, 16);   // 17th smallest
    float kthB = __shfl_sync(FULL, dlB, 16);

#pragma unroll 2
    for (int t = 1; t < NN / 32; ++t) {
        const float4 c = sh[t * 32 + lane];
        float dA = fmaf(-2.0f, fmaf(qA.z, c.z, fmaf(qA.y, c.y, qA.x * c.x)), c.w);
        float dB = fmaf(-2.0f, fmaf(qB.z, c.z, fmaf(qB.y, c.y, qB.x * c.x)), c.w);

        unsigned mA = __ballot_sync(FULL, dA < kthA);
        unsigned mB = __ballot_sync(FULL, dB < kthB);
        if (mA) {
            do {
                const int src = __ffs(mA) - 1;
                mA &= mA - 1;
                const float dc = __shfl_sync(FULL, dA, src);
                const int   mc = t * 32 + src;
                const float up_d = __shfl_up_sync(FULL, dlA, 1);
                const int   up_i = __shfl_up_sync(FULL, ilA, 1);
                const bool here = dc < dlA;                 // strict: stable tie-break
                const bool prev = (lane > 0) && (dc < up_d);
                dlA = here ? (prev ? up_d : dc) : dlA;
                ilA = here ? (prev ? up_i : mc) : ilA;
            } while (mA);
            kthA = __shfl_sync(FULL, dlA, 16);
        }
        if (mB) {
            do {
                const int src = __ffs(mB) - 1;
                mB &= mB - 1;
                const float dc = __shfl_sync(FULL, dB, src);
                const int   mc = t * 32 + src;
                const float up_d = __shfl_up_sync(FULL, dlB, 1);
                const int   up_i = __shfl_up_sync(FULL, ilB, 1);
                const bool here = dc < dlB;
                const bool prev = (lane > 0) && (dc < up_d);
                dlB = here ? (prev ? up_d : dc) : dlB;
                ilB = here ? (prev ? up_i : mc) : ilB;
            } while (mB);
            kthB = __shfl_sync(FULL, dlB, 16);
        }
    }

    if (lane >= 1 && lane <= KK1) {
        g_idx[((size_t)b * NN + qAi) * KK1 + (lane - 1)] = ilA;
        g_idx[((size_t)b * NN + qBi) * KK1 + (lane - 1)] = ilB;
    }
}

// ---------------- SGEMM with packed f32x2 FMA (R8 exact) ----------------
__global__ __launch_bounds__(256, 2) void gemm_kernel(const float* __restrict__ xyz,
                                                      const float* __restrict__ feature) {
    __shared__ __align__(16) float As[16][128];
    __shared__ __align__(16) float Bs[16][128];

    const int tid = threadIdx.x;
    const int tr = tid >> 4;
    const int tc = tid & 15;
    const int p0 = blockIdx.x * 128;
    const int b  = p0 >> 12;
    const int nl = p0 & (NN - 1);
    const int rowbase = blockIdx.y * 128;

    const int la_k = tid >> 4;
    const int la_r = (tid & 15) * 8;
    const int lb_k = tid >> 4;
    const int lb_j = (tid & 15) * 8;

    u64 acc[8][4];
#pragma unroll
    for (int i = 0; i < 8; ++i)
#pragma unroll
        for (int j = 0; j < 4; ++j) acc[i][j] = 0ull;

    float4 pa0, pa1, pb0, pb1;
    {
        const float* srcA = g_WcT + la_k * RWS + rowbase + la_r;
        pa0 = *(const float4*)srcA; pa1 = *(const float4*)(srcA + 4);
        int kg = lb_k;
        const float* row = (kg < 3) ? (xyz + ((size_t)b * 3 + kg) * NN)
                                    : (feature + ((size_t)b * CC + (kg - 3)) * NN);
        pb0 = *(const float4*)(row + nl + lb_j);
        pb1 = *(const float4*)(row + nl + lb_j + 4);
    }

    for (int kt = 0; kt < KPAD / 16; ++kt) {
        *(float4*)&As[la_k][la_r]     = pa0;
        *(float4*)&As[la_k][la_r + 4] = pa1;
        *(float4*)&Bs[lb_k][lb_j]     = pb0;
        *(float4*)&Bs[lb_k][lb_j + 4] = pb1;
        __syncthreads();
        if (kt + 1 < KPAD / 16) {
            const float* srcA = g_WcT + ((kt + 1) * 16 + la_k) * RWS + rowbase + la_r;
            pa0 = *(const float4*)srcA; pa1 = *(const float4*)(srcA + 4);
            int kg = (kt + 1) * 16 + lb_k;
            if (kg < KDIM) {
                const float* row = (kg < 3) ? (xyz + ((size_t)b * 3 + kg) * NN)
                                            : (feature + ((size_t)b * CC + (kg - 3)) * NN);
                pb0 = *(const float4*)(row + nl + lb_j);
                pb1 = *(const float4*)(row + nl + lb_j + 4);
            } else {
                pb0 = make_float4(0.f, 0.f, 0.f, 0.f);
                pb1 = pb0;
            }
        }
#pragma unroll
        for (int k = 0; k < 16; ++k) {
            float4 a0 = *(const float4*)&As[k][tr * 8];
            float4 a1 = *(const float4*)&As[k][tr * 8 + 4];
            ulonglong2 b0 = *(const ulonglong2*)&Bs[k][tc * 8];
            ulonglong2 b1 = *(const ulonglong2*)&Bs[k][tc * 8 + 4];
            u64 bp[4] = {b0.x, b0.y, b1.x, b1.y};
            float ar[8] = {a0.x, a0.y, a0.z, a0.w, a1.x, a1.y, a1.z, a1.w};
#pragma unroll
            for (int i = 0; i < 8; ++i) {
                u64 a2 = dup2(ar[i]);
#pragma unroll
                for (int j = 0; j < 4; ++j)
                    acc[i][j] = ffma2(a2, bp[j], acc[i][j]);
            }
        }
        __syncthreads();
    }

    const int gr = rowbase + tr * 8;
    float bias[8];
#pragma unroll
    for (int i = 0; i < 8; ++i) bias[i] = g_bias[gr + i];
    float r_[8][8];
#pragma unroll
    for (int i = 0; i < 8; ++i)
#pragma unroll
        for (int j = 0; j < 4; ++j)
            unpack2(acc[i][j], r_[i][2 * j], r_[i][2 * j + 1]);
#pragma unroll
    for (int j = 0; j < 8; ++j) {
        int p = p0 + tc * 8 + j;
        float* dst = g_P + (size_t)p * RWS + gr;
        float4 v0 = make_float4(r_[0][j] + bias[0], r_[1][j] + bias[1],
                                r_[2][j] + bias[2], r_[3][j] + bias[3]);
        float4 v1 = make_float4(r_[4][j] + bias[4], r_[5][j] + bias[5],
                                r_[6][j] + bias[6], r_[7][j] + bias[7]);
        *(float4*)dst       = v0;
        *(float4*)(dst + 4) = v1;
    }
}

// ---------------- attention (R8 exact) ----------------
#define WARP_FLOATS 1632
#define SM_RES      (8*WARP_FLOATS)
#define SM_ATTN_TOT (SM_RES + 8*132)

__global__ __launch_bounds__(256, 3) void attn_kernel(const float* __restrict__ feature,
                                                      const float* __restrict__ b1,
                                                      float* __restrict__ out) {
    extern __shared__ __align__(16) float sm[];
    const int tid = threadIdx.x;
    const int w = tid >> 5, l = tid & 31;
    float* qw   = sm + w * WARP_FLOATS;
    float* kw   = qw + 8 * 68;
    float* resT = sm + SM_RES;

    const int gp = blockIdx.x * 8 + w;
    const int b  = gp >> 12;
    const int* ip = g_idx + (size_t)gp * KK1;
    const float* Pbase = g_P + ((size_t)(b << 12)) * RWS;
    const float* Sp    = g_P + (size_t)gp * RWS + 256;

    int c[16];
    {
        int4 t0 = ((const int4*)ip)[0]; int4 t1 = ((const int4*)ip)[1];
        int4 t2 = ((const int4*)ip)[2]; int4 t3 = ((const int4*)ip)[3];
        c[0]=t0.x; c[1]=t0.y; c[2]=t0.z; c[3]=t0.w;
        c[4]=t1.x; c[5]=t1.y; c[6]=t1.z; c[7]=t1.w;
        c[8]=t2.x; c[9]=t2.y; c[10]=t2.z; c[11]=t2.w;
        c[12]=t3.x; c[13]=t3.y; c[14]=t3.z; c[15]=t3.w;
    }

    // ---- gather q = Pq[c] + Sq ----
    {
        int a = l >> 2, qt = l & 3;
        const float4* src = (const float4*)(Pbase + (size_t)c[a] * RWS) + qt * 4;
        const float4* s4  = (const float4*)Sp + qt * 4;
        float4* dst = (float4*)(qw + a * 68 + qt * 16);
#pragma unroll
        for (int f = 0; f < 4; ++f) {
            float4 p = src[f], s = s4[f];
            dst[f] = make_float4(p.x + s.x, p.y + s.y, p.z + s.z, p.w + s.w);
        }
    }
    // ---- gather k = Pk[c] + Sk ----
    {
        int j = l >> 1, h = l & 1;
        const float4* src = (const float4*)(Pbase + (size_t)c[j] * RWS + 64 + h * 32);
        const float4* s4  = (const float4*)(Sp + 64 + h * 32);
        float4* dst = (float4*)(kw + j * 68 + h * 32);
#pragma unroll
        for (int f = 0; f < 8; ++f) {
            float4 p = src[f], s = s4[f];
            dst[f] = make_float4(p.x + s.x, p.y + s.y, p.z + s.z, p.w + s.w);
        }
    }
    __syncwarp();

    // ---- logits with packed f32x2 ----
    const int nq = l & 7, jg = l >> 3;
    u64 acc2[4] = {0ull, 0ull, 0ull, 0ull};
    const ulonglong2* qrow = (const ulonglong2*)(qw + nq * 68);
#pragma unroll
    for (int dc = 0; dc < 4; ++dc) {
        ulonglong2 qa = qrow[dc * 4 + 0], qb = qrow[dc * 4 + 1];
        ulonglong2 qc = qrow[dc * 4 + 2], qd = qrow[dc * 4 + 3];
#pragma unroll
        for (int j4 = 0; j4 < 4; ++j4) {
            const ulonglong2* kr = (const ulonglong2*)(kw + (j4 * 4 + jg) * 68);
            ulonglong2 ka = kr[dc * 4 + 0], kb = kr[dc * 4 + 1];
            ulonglong2 kc = kr[dc * 4 + 2], kd = kr[dc * 4 + 3];
            u64 s = acc2[j4];
            s = ffma2(qa.x, ka.x, s); s = ffma2(qa.y, ka.y, s);
            s = ffma2(qb.x, kb.x, s); s = ffma2(qb.y, kb.y, s);
            s = ffma2(qc.x, kc.x, s); s = ffma2(qc.y, kc.y, s);
            s = ffma2(qd.x, kd.x, s); s = ffma2(qd.y, kd.y, s);
            acc2[j4] = s;
        }
    }
    float acc[4];
#pragma unroll
    for (int j4 = 0; j4 < 4; ++j4) {
        float lo, hi; unpack2(acc2[j4], lo, hi);
        acc[j4] = lo + hi;
    }

    // ---- softmax over j per query row nq ----
    float mx = fmaxf(fmaxf(acc[0], acc[1]), fmaxf(acc[2], acc[3]));
    mx = fmaxf(mx, __shfl_xor_sync(0xffffffffu, mx, 8));
    mx = fmaxf(mx, __shfl_xor_sync(0xffffffffu, mx, 16));
    float e[4], ssum = 0.f;
#pragma unroll
    for (int j4 = 0; j4 < 4; ++j4) { e[j4] = __expf(acc[j4] - mx); ssum += e[j4]; }
    ssum += __shfl_xor_sync(0xffffffffu, ssum, 8);
    ssum += __shfl_xor_sync(0xffffffffu, ssum, 16);
    float inv = 1.0f / ssum;
    float wj[4];
#pragma unroll
    for (int j4 = 0; j4 < 4; ++j4) wj[j4] = e[j4] * inv;

    // ---- colsum over the 8 queries ----
#pragma unroll
    for (int off = 1; off < 8; off <<= 1)
#pragma unroll
        for (int j4 = 0; j4 < 4; ++j4)
            wj[j4] += __shfl_xor_sync(0xffffffffu, wj[j4], off);

    // ---- res128 = sum_j w[j]*PvProj[c_j] + wsum*SvProj (packed) ----
    u64 av0 = 0ull, av1 = 0ull;
#pragma unroll
    for (int j = 0; j < 16; ++j) {
        float wjv = __shfl_sync(0xffffffffu, wj[j >> 2], (j & 3) * 8);
        u64 w2 = dup2(wjv);
        ulonglong2 vv = *(const ulonglong2*)(Pbase + (size_t)c[j] * RWS + 128 + 4 * l);
        av0 = ffma2(w2, vv.x, av0);
        av1 = ffma2(w2, vv.y, av1);
    }
    float wsum = wj[0] + wj[1] + wj[2] + wj[3];
    wsum += __shfl_xor_sync(0xffffffffu, wsum, 8);
    wsum += __shfl_xor_sync(0xffffffffu, wsum, 16);
    {
        u64 w2 = dup2(wsum);
        ulonglong2 sv = *(const ulonglong2*)(Sp + 128 + 4 * l);
        av0 = ffma2(w2, sv.x, av0);
        av1 = ffma2(w2, sv.y, av1);
    }
    {
        float4 r;
        unpack2(av0, r.x, r.y);
        unpack2(av1, r.z, r.w);
        *(float4*)(resT + w * 132 + 4 * l) = r;
    }
    __syncthreads();

    // ---- out = res + b1 + feature ----
    const int o  = tid >> 1;
    const int pg = (tid & 1) * 4;
    const int gp0 = blockIdx.x * 8;
    const int bb = gp0 >> 12, nl = gp0 & (NN - 1);
    size_t base = ((size_t)bb * CC + o) * NN + nl + pg;
    float bo = b1[o];
    float4 fv = *(const float4*)(feature + base);
    float4 ov;
    ov.x = resT[(pg + 0) * 132 + o] + bo + fv.x;
    ov.y = resT[(pg + 1) * 132 + o] + bo + fv.y;
    ov.z = resT[(pg + 2) * 132 + o] + bo + fv.z;
    ov.w = resT[(pg + 3) * 132 + o] + bo + fv.w;
    *(float4*)(out + base) = ov;
}

// ---------------- launch: plain serial, single stream (R8 topology) ----------------
extern "C" void kernel_launch(void* const* d_in, const int* in_sizes, int n_in,
                              void* d_out, int out_size) {
    const float* feature = (const float*)d_in[0];
    const float* xyz     = (const float*)d_in[1];
    const float* wq      = (const float*)d_in[2];
    const float* bq      = (const float*)d_in[3];
    const float* wk      = (const float*)d_in[4];
    const float* bk      = (const float*)d_in[5];
    const float* wv      = (const float*)d_in[6];
    const float* bv      = (const float*)d_in[7];
    const float* w1      = (const float*)d_in[8];
    const float* b1      = (const float*)d_in[9];
    float* out = (float*)d_out;

    static bool attr_done = false;
    if (!attr_done) {
        cudaFuncSetAttribute(knn_kernel,  cudaFuncAttributeMaxDynamicSharedMemorySize, NN * 16);
        cudaFuncSetAttribute(attn_kernel, cudaFuncAttributeMaxDynamicSharedMemorySize, SM_ATTN_TOT * 4);
        attr_done = true;
    }

    const int knn_smem  = NN * 16;
    const int attn_smem = SM_ATTN_TOT * 4;

    prep_kernel<<<KPAD + 1, 512>>>(wq, wk, wv, bq, bk, bv, w1);
    knn_kernel<<<BB * 128, 512, knn_smem>>>(xyz);
    gemm_kernel<<<dim3(NPTS / 128, RWS / 128), 256>>>(xyz, feature);
    attn_kernel<<<NPTS / 8, 256, attn_smem>>>(feature, b1, out);
}

// round 16
// speedup vs baseline: 1.3303x; 1.0064x over previous
#include <cuda_runtime.h>
#include <math.h>

#define BB   4
#define NN   4096
#define CC   128
#define KK1  16
#define KK2  8
#define TDD  64
#define KDIM 131
#define KPAD 144
#define RWS  512
#define NPTS (BB*NN)

typedef unsigned long long u64;

__device__ __forceinline__ u64 ffma2(u64 a, u64 b, u64 c) {
    u64 d;
    asm("fma.rn.f32x2 %0, %1, %2, %3;" : "=l"(d) : "l"(a), "l"(b), "l"(c));
    return d;
}
__device__ __forceinline__ u64 dup2(float x) {
    u64 d;
    asm("mov.b64 %0, {%1, %1};" : "=l"(d) : "r"(__float_as_int(x)));
    return d;
}
__device__ __forceinline__ void unpack2(u64 v, float& lo, float& hi) {
    int a, b;
    asm("mov.b64 {%0, %1}, %2;" : "=r"(a), "=r"(b) : "l"(v));
    lo = __int_as_float(a); hi = __int_as_float(b);
}

// ---------------- scratch ----------------
__device__ int   g_idx[NPTS*KK1];
// per point rows: [0:64)Pq [64:128)Pk [128:256)PvProj [256:320)Sq [320:384)Sk [384:512)SvProj
__device__ float g_P[(size_t)NPTS*RWS];
__device__ float g_WcT[KPAD*RWS];
__device__ float g_bias[RWS];

// ---------------- prep: smem-tiled (one block per k-row; block 144 = bias) ----------------
__global__ __launch_bounds__(512) void prep_kernel(const float* __restrict__ wq,
                                                   const float* __restrict__ wk,
                                                   const float* __restrict__ wv,
                                                   const float* __restrict__ bq,
                                                   const float* __restrict__ bk,
                                                   const float* __restrict__ bv,
                                                   const float* __restrict__ w1) {
    __shared__ float w1s[CC * 65];                 // padded stride 65: conflict-free
    __shared__ float wvP[TDD];
    __shared__ float wvS[TDD];
    const int tid = threadIdx.x;
    const int k = blockIdx.x;

    for (int i = tid; i < CC * TDD; i += 512) {
        int o = i >> 6, m = i & 63;
        w1s[o * 65 + m] = w1[i];
    }

    if (k < KPAD) {
        if (tid < 2 * TDD) {
            int m = tid & 63;
            const float* row = wv + m * 262;
            if (k < KDIM) {
                float p = (k < 3) ? row[k] : row[6 + (k - 3)];
                float s = (k < 3) ? (row[3 + k] - row[k])
                                  : (row[134 + (k - 3)] - row[6 + (k - 3)]);
                if (tid < TDD) wvP[m] = p; else wvS[m] = s;
            } else {
                if (tid < TDD) wvP[m] = 0.f; else wvS[m] = 0.f;
            }
        }
        __syncthreads();

        const int r = tid;
        float val = 0.f;
        if (k < KDIM) {
            if (r < 128) {
                const float* w = (r < 64) ? wq : wk;
                const float* row = w + (r & 63) * 262;
                val = (k < 3) ? row[k] : row[6 + (k - 3)];
            } else if (r < 256) {
                const float* wr = w1s + (r - 128) * 65;
                float s = 0.f;
#pragma unroll 16
                for (int m = 0; m < TDD; ++m) s = fmaf(wr[m], wvP[m], s);
                val = s;
            } else if (r < 384) {
                const float* w = (r < 320) ? wq : wk;
                const float* row = w + (r & 63) * 262;
                val = (k < 3) ? (row[3 + k] - row[k])
                              : (row[134 + (k - 3)] - row[6 + (k - 3)]);
            } else {
                const float* wr = w1s + (r - 384) * 65;
                float s = 0.f;
#pragma unroll 16
                for (int m = 0; m < TDD; ++m) s = fmaf(wr[m], wvS[m], s);
                val = s;
            }
        }
        g_WcT[(k << 9) + r] = val;
    } else {
        __syncthreads();
        const int i = tid;
        float bval = 0.f;
        if (i >= 256 && i < 320) bval = bq[i - 256];
        else if (i >= 320 && i < 384) bval = bk[i - 320];
        else if (i >= 384) {
            const float* wr = w1s + (i - 384) * 65;
            float s = 0.f;
#pragma unroll 16
            for (int m = 0; m < TDD; ++m) s = fmaf(wr[m], bv[m], s);
            bval = s;
        }
        g_bias[i] = bval;
    }
}

// ---------------- kNN: warp per 2 queries, smem tile, top-17, 3-FMA distances ------------
// Self is NOT excluded: d(self) = -|q|^2 is the strict minimum -> rank 0 always.
// Emit ranks 1..16 (== reference dropping idx[...,0]).
__global__ __launch_bounds__(512) void knn_kernel(const float* __restrict__ xyz) {
    extern __shared__ float4 sh[];                 // 4096 * 16B = 64KB
    const unsigned FULL = 0xffffffffu;
    const int b = blockIdx.x >> 7;
    const int qbase = (blockIdx.x & 127) * 32;
    const int tid = threadIdx.x;
    const int w = tid >> 5, lane = tid & 31;
    const float* xb = xyz + (size_t)b * 3 * NN;

    for (int i = tid; i < NN; i += 512) {
        float x = xb[i], y = xb[NN + i], z = xb[2 * NN + i];
        float sq = fmaf(z, z, fmaf(y, y, x * x));
        sh[i] = make_float4(x, y, z, sq);
    }
    __syncthreads();

    const int qAi = qbase + 2 * w;
    const int qBi = qAi + 1;
    const float4 qA = sh[qAi];
    const float4 qB = sh[qBi];
    // hoisted -2*q components: d = fma(ax,cx, fma(ay,cy, fma(az,cz, cw)))
    const float ax = -2.0f * qA.x, ay = -2.0f * qA.y, az = -2.0f * qA.z;
    const float bx = -2.0f * qB.x, by = -2.0f * qB.y, bz = -2.0f * qB.z;

    float dlA, dlB;
    int   ilA = lane, ilB = lane;
    {
        float4 c = sh[lane];
        dlA = fmaf(ax, c.x, fmaf(ay, c.y, fmaf(az, c.z, c.w)));
        dlB = fmaf(bx, c.x, fmaf(by, c.y, fmaf(bz, c.z, c.w)));
    }
#pragma unroll
    for (int k = 2; k <= 32; k <<= 1) {
#pragma unroll
        for (int j = k >> 1; j > 0; j >>= 1) {
            float odA = __shfl_xor_sync(FULL, dlA, j);
            int   oiA = __shfl_xor_sync(FULL, ilA, j);
            float odB = __shfl_xor_sync(FULL, dlB, j);
            int   oiB = __shfl_xor_sync(FULL, ilB, j);
            bool keepLt = (((lane & k) == 0) == ((lane & j) == 0));
            bool ltA = (odA < dlA) || (odA == dlA && oiA < ilA);
            bool ltB = (odB < dlB) || (odB == dlB && oiB < ilB);
            bool swA = keepLt ? ltA : !ltA;
            bool swB = keepLt ? ltB : !ltB;
            if (swA) { dlA = odA; ilA = oiA; }
            if (swB) { dlB = odB; ilB = oiB; }
        }
    }
    float kthA = __shfl_sync(FULL, dlA, 16);   // 17th smallest
    float kthB = __shfl_sync(FULL, dlB, 16);

#pragma unroll 2
    for (int t = 1; t < NN / 32; ++t) {
        const float4 c = sh[t * 32 + lane];
        float dA = fmaf(ax, c.x, fmaf(ay, c.y, fmaf(az, c.z, c.w)));
        float dB = fmaf(bx, c.x, fmaf(by, c.y, fmaf(bz, c.z, c.w)));

        unsigned mA = __ballot_sync(FULL, dA < kthA);
        unsigned mB = __ballot_sync(FULL, dB < kthB);
        if (mA) {
            do {
                const int src = __ffs(mA) - 1;
                mA &= mA - 1;
                const float dc = __shfl_sync(FULL, dA, src);
                const int   mc = t * 32 + src;
                const float up_d = __shfl_up_sync(FULL, dlA, 1);
                const int   up_i = __shfl_up_sync(FULL, ilA, 1);
                const bool here = dc < dlA;                 // strict: stable tie-break
                const bool prev = (lane > 0) && (dc < up_d);
                dlA = here ? (prev ? up_d : dc) : dlA;
                ilA = here ? (prev ? up_i : mc) : ilA;
            } while (mA);
            kthA = __shfl_sync(FULL, dlA, 16);
        }
        if (mB) {
            do {
                const int src = __ffs(mB) - 1;
                mB &= mB - 1;
                const float dc = __shfl_sync(FULL, dB, src);
                const int   mc = t * 32 + src;
                const float up_d = __shfl_up_sync(FULL, dlB, 1);
                const int   up_i = __shfl_up_sync(FULL, ilB, 1);
                const bool here = dc < dlB;
                const bool prev = (lane > 0) && (dc < up_d);
                dlB = here ? (prev ? up_d : dc) : dlB;
                ilB = here ? (prev ? up_i : mc) : ilB;
            } while (mB);
            kthB = __shfl_sync(FULL, dlB, 16);
        }
    }

    if (lane >= 1 && lane <= KK1) {
        g_idx[((size_t)b * NN + qAi) * KK1 + (lane - 1)] = ilA;
        g_idx[((size_t)b * NN + qBi) * KK1 + (lane - 1)] = ilB;
    }
}

// ---------------- SGEMM with packed f32x2 FMA (R8 exact) ----------------
__global__ __launch_bounds__(256, 2) void gemm_kernel(const float* __restrict__ xyz,
                                                      const float* __restrict__ feature) {
    __shared__ __align__(16) float As[16][128];
    __shared__ __align__(16) float Bs[16][128];

    const int tid = threadIdx.x;
    const int tr = tid >> 4;
    const int tc = tid & 15;
    const int p0 = blockIdx.x * 128;
    const int b  = p0 >> 12;
    const int nl = p0 & (NN - 1);
    const int rowbase = blockIdx.y * 128;

    const int la_k = tid >> 4;
    const int la_r = (tid & 15) * 8;
    const int lb_k = tid >> 4;
    const int lb_j = (tid & 15) * 8;

    u64 acc[8][4];
#pragma unroll
    for (int i = 0; i < 8; ++i)
#pragma unroll
        for (int j = 0; j < 4; ++j) acc[i][j] = 0ull;

    float4 pa0, pa1, pb0, pb1;
    {
        const float* srcA = g_WcT + la_k * RWS + rowbase + la_r;
        pa0 = *(const float4*)srcA; pa1 = *(const float4*)(srcA + 4);
        int kg = lb_k;
        const float* row = (kg < 3) ? (xyz + ((size_t)b * 3 + kg) * NN)
                                    : (feature + ((size_t)b * CC + (kg - 3)) * NN);
        pb0 = *(const float4*)(row + nl + lb_j);
        pb1 = *(const float4*)(row + nl + lb_j + 4);
    }

    for (int kt = 0; kt < KPAD / 16; ++kt) {
        *(float4*)&As[la_k][la_r]     = pa0;
        *(float4*)&As[la_k][la_r + 4] = pa1;
        *(float4*)&Bs[lb_k][lb_j]     = pb0;
        *(float4*)&Bs[lb_k][lb_j + 4] = pb1;
        __syncthreads();
        if (kt + 1 < KPAD / 16) {
            const float* srcA = g_WcT + ((kt + 1) * 16 + la_k) * RWS + rowbase + la_r;
            pa0 = *(const float4*)srcA; pa1 = *(const float4*)(srcA + 4);
            int kg = (kt + 1) * 16 + lb_k;
            if (kg < KDIM) {
                const float* row = (kg < 3) ? (xyz + ((size_t)b * 3 + kg) * NN)
                                            : (feature + ((size_t)b * CC + (kg - 3)) * NN);
                pb0 = *(const float4*)(row + nl + lb_j);
                pb1 = *(const float4*)(row + nl + lb_j + 4);
            } else {
                pb0 = make_float4(0.f, 0.f, 0.f, 0.f);
                pb1 = pb0;
            }
        }
#pragma unroll
        for (int k = 0; k < 16; ++k) {
            float4 a0 = *(const float4*)&As[k][tr * 8];
            float4 a1 = *(const float4*)&As[k][tr * 8 + 4];
            ulonglong2 b0 = *(const ulonglong2*)&Bs[k][tc * 8];
            ulonglong2 b1 = *(const ulonglong2*)&Bs[k][tc * 8 + 4];
            u64 bp[4] = {b0.x, b0.y, b1.x, b1.y};
            float ar[8] = {a0.x, a0.y, a0.z, a0.w, a1.x, a1.y, a1.z, a1.w};
#pragma unroll
            for (int i = 0; i < 8; ++i) {
                u64 a2 = dup2(ar[i]);
#pragma unroll
                for (int j = 0; j < 4; ++j)
                    acc[i][j] = ffma2(a2, bp[j], acc[i][j]);
            }
        }
        __syncthreads();
    }

    const int gr = rowbase + tr * 8;
    float bias[8];
#pragma unroll
    for (int i = 0; i < 8; ++i) bias[i] = g_bias[gr + i];
    float r_[8][8];
#pragma unroll
    for (int i = 0; i < 8; ++i)
#pragma unroll
        for (int j = 0; j < 4; ++j)
            unpack2(acc[i][j], r_[i][2 * j], r_[i][2 * j + 1]);
#pragma unroll
    for (int j = 0; j < 8; ++j) {
        int p = p0 + tc * 8 + j;
        float* dst = g_P + (size_t)p * RWS + gr;
        float4 v0 = make_float4(r_[0][j] + bias[0], r_[1][j] + bias[1],
                                r_[2][j] + bias[2], r_[3][j] + bias[3]);
        float4 v1 = make_float4(r_[4][j] + bias[4], r_[5][j] + bias[5],
                                r_[6][j] + bias[6], r_[7][j] + bias[7]);
        *(float4*)dst       = v0;
        *(float4*)(dst + 4) = v1;
    }
}

// ---------------- attention: neighbor indices in smem, 4 blocks/SM ----------------
#define WARP_FLOATS 1632
#define SM_RES      (8*WARP_FLOATS)
#define SM_CI       (SM_RES + 8*132)
#define SM_ATTN_TOT (SM_CI + 8*16)

__global__ __launch_bounds__(256, 4) void attn_kernel(const float* __restrict__ feature,
                                                      const float* __restrict__ b1,
                                                      float* __restrict__ out) {
    extern __shared__ __align__(16) float sm[];
    const int tid = threadIdx.x;
    const int w = tid >> 5, l = tid & 31;
    float* qw   = sm + w * WARP_FLOATS;
    float* kw   = qw + 8 * 68;
    float* resT = sm + SM_RES;
    int*   cs   = (int*)(sm + SM_CI) + w * 16;

    const int gp = blockIdx.x * 8 + w;
    const int b  = gp >> 12;
    const int* ip = g_idx + (size_t)gp * KK1;
    const float* Pbase = g_P + ((size_t)(b << 12)) * RWS;
    const float* Sp    = g_P + (size_t)gp * RWS + 256;

    // stage neighbor indices into smem (frees 16 registers for 4-block occupancy)
    if (l < 4) {
        ((int4*)cs)[l] = ((const int4*)ip)[l];
    }
    __syncwarp();

    // ---- gather q = Pq[c] + Sq ----
    {
        int a = l >> 2, qt = l & 3;
        const float4* src = (const float4*)(Pbase + (size_t)cs[a] * RWS) + qt * 4;
        const float4* s4  = (const float4*)Sp + qt * 4;
        float4* dst = (float4*)(qw + a * 68 + qt * 16);
#pragma unroll
        for (int f = 0; f < 4; ++f) {
            float4 p = src[f], s = s4[f];
            dst[f] = make_float4(p.x + s.x, p.y + s.y, p.z + s.z, p.w + s.w);
        }
    }
    // ---- gather k = Pk[c] + Sk ----
    {
        int j = l >> 1, h = l & 1;
        const float4* src = (const float4*)(Pbase + (size_t)cs[j] * RWS + 64 + h * 32);
        const float4* s4  = (const float4*)(Sp + 64 + h * 32);
        float4* dst = (float4*)(kw + j * 68 + h * 32);
#pragma unroll
        for (int f = 0; f < 8; ++f) {
            float4 p = src[f], s = s4[f];
            dst[f] = make_float4(p.x + s.x, p.y + s.y, p.z + s.z, p.w + s.w);
        }
    }
    __syncwarp();

    // ---- logits with packed f32x2 ----
    const int nq = l & 7, jg = l >> 3;
    u64 acc2[4] = {0ull, 0ull, 0ull, 0ull};
    const ulonglong2* qrow = (const ulonglong2*)(qw + nq * 68);
#pragma unroll
    for (int dc = 0; dc < 4; ++dc) {
        ulonglong2 qa = qrow[dc * 4 + 0], qb = qrow[dc * 4 + 1];
        ulonglong2 qc = qrow[dc * 4 + 2], qd = qrow[dc * 4 + 3];
#pragma unroll
        for (int j4 = 0; j4 < 4; ++j4) {
            const ulonglong2* kr = (const ulonglong2*)(kw + (j4 * 4 + jg) * 68);
            ulonglong2 ka = kr[dc * 4 + 0], kb = kr[dc * 4 + 1];
            ulonglong2 kc = kr[dc * 4 + 2], kd = kr[dc * 4 + 3];
            u64 s = acc2[j4];
            s = ffma2(qa.x, ka.x, s); s = ffma2(qa.y, ka.y, s);
            s = ffma2(qb.x, kb.x, s); s = ffma2(qb.y, kb.y, s);
            s = ffma2(qc.x, kc.x, s); s = ffma2(qc.y, kc.y, s);
            s = ffma2(qd.x, kd.x, s); s = ffma2(qd.y, kd.y, s);
            acc2[j4] = s;
        }
    }
    float acc[4];
#pragma unroll
    for (int j4 = 0; j4 < 4; ++j4) {
        float lo, hi; unpack2(acc2[j4], lo, hi);
        acc[j4] = lo + hi;
    }

    // ---- softmax over j per query row nq ----
    float mx = fmaxf(fmaxf(acc[0], acc[1]), fmaxf(acc[2], acc[3]));
    mx = fmaxf(mx, __shfl_xor_sync(0xffffffffu, mx, 8));
    mx = fmaxf(mx, __shfl_xor_sync(0xffffffffu, mx, 16));
    float e[4], ssum = 0.f;
#pragma unroll
    for (int j4 = 0; j4 < 4; ++j4) { e[j4] = __expf(acc[j4] - mx); ssum += e[j4]; }
    ssum += __shfl_xor_sync(0xffffffffu, ssum, 8);
    ssum += __shfl_xor_sync(0xffffffffu, ssum, 16);
    float inv = 1.0f / ssum;
    float wj[4];
#pragma unroll
    for (int j4 = 0; j4 < 4; ++j4) wj[j4] = e[j4] * inv;

    // ---- colsum over the 8 queries ----
#pragma unroll
    for (int off = 1; off < 8; off <<= 1)
#pragma unroll
        for (int j4 = 0; j4 < 4; ++j4)
            wj[j4] += __shfl_xor_sync(0xffffffffu, wj[j4], off);

    // ---- res128 = sum_j w[j]*PvProj[c_j] + wsum*SvProj (packed) ----
    u64 av0 = 0ull, av1 = 0ull;
#pragma unroll
    for (int j = 0; j < 16; ++j) {
        float wjv = __shfl_sync(0xffffffffu, wj[j >> 2], (j & 3) * 8);
        u64 w2 = dup2(wjv);
        ulonglong2 vv = *(const ulonglong2*)(Pbase + (size_t)cs[j] * RWS + 128 + 4 * l);
        av0 = ffma2(w2, vv.x, av0);
        av1 = ffma2(w2, vv.y, av1);
    }
    float wsum = wj[0] + wj[1] + wj[2] + wj[3];
    wsum += __shfl_xor_sync(0xffffffffu, wsum, 8);
    wsum += __shfl_xor_sync(0xffffffffu, wsum, 16);
    {
        u64 w2 = dup2(wsum);
        ulonglong2 sv = *(const ulonglong2*)(Sp + 128 + 4 * l);
        av0 = ffma2(w2, sv.x, av0);
        av1 = ffma2(w2, sv.y, av1);
    }
    {
        float4 r;
        unpack2(av0, r.x, r.y);
        unpack2(av1, r.z, r.w);
        *(float4*)(resT + w * 132 + 4 * l) = r;
    }
    __syncthreads();

    // ---- out = res + b1 + feature ----
    const int o  = tid >> 1;
    const int pg = (tid & 1) * 4;
    const int gp0 = blockIdx.x * 8;
    const int bb = gp0 >> 12, nl = gp0 & (NN - 1);
    size_t base = ((size_t)bb * CC + o) * NN + nl + pg;
    float bo = b1[o];
    float4 fv = *(const float4*)(feature + base);
    float4 ov;
    ov.x = resT[(pg + 0) * 132 + o] + bo + fv.x;
    ov.y = resT[(pg + 1) * 132 + o] + bo + fv.y;
    ov.z = resT[(pg + 2) * 132 + o] + bo + fv.z;
    ov.w = resT[(pg + 3) * 132 + o] + bo + fv.w;
    *(float4*)(out + base) = ov;
}

// ---------------- launch: plain serial, single stream ----------------
extern "C" void kernel_launch(void* const* d_in, const int* in_sizes, int n_in,
                              void* d_out, int out_size) {
    const float* feature = (const float*)d_in[0];
    const float* xyz     = (const float*)d_in[1];
    const float* wq      = (const float*)d_in[2];
    const float* bq      = (const float*)d_in[3];
    const float* wk      = (const float*)d_in[4];
    const float* bk      = (const float*)d_in[5];
    const float* wv      = (const float*)d_in[6];
    const float* bv      = (const float*)d_in[7];
    const float* w1      = (const float*)d_in[8];
    const float* b1      = (const float*)d_in[9];
    float* out = (float*)d_out;

    static bool attr_done = false;
    if (!attr_done) {
        cudaFuncSetAttribute(knn_kernel,  cudaFuncAttributeMaxDynamicSharedMemorySize, NN * 16);
        cudaFuncSetAttribute(attn_kernel, cudaFuncAttributeMaxDynamicSharedMemorySize, SM_ATTN_TOT * 4);
        attr_done = true;
    }

    const int knn_smem  = NN * 16;
    const int attn_smem = SM_ATTN_TOT * 4;

    prep_kernel<<<KPAD + 1, 512>>>(wq, wk, wv, bq, bk, bv, w1);
    knn_kernel<<<BB * 128, 512, knn_smem>>>(xyz);
    gemm_kernel<<<dim3(NPTS / 128, RWS / 128), 256>>>(xyz, feature);
    attn_kernel<<<NPTS / 8, 256, attn_smem>>>(feature, b1, out);
}